// round 14
// baseline (speedup 1.0000x reference)
#include <cuda_runtime.h>
#include <cuda_bf16.h>
#include <math.h>
#include <stdint.h>

#define TT 2048
#define HH 4096
#define NH 32
#define HD 128
#define II 11008
#define ATTN_TOPK 16
#define MLP_TOPK 2048
#define QB 8

// ---------------- scratch ----------------
__device__ float g_hs[TT * HH];
__device__ float g_q[TT * HH];
__device__ float g_k[TT * HH];
__device__ float g_v[TT * HH];
__device__ float g_attn[TT * HH];
__device__ float g_res2[TT * HH];
__device__ float g_hlogit[TT * NH];
__device__ float g_headmask[TT * NH];
__device__ float g_mlogit[TT * II];
__device__ float g_fcmask[TT * II];
__device__ float g_gate[TT * II];
__device__ float g_up[TT * II];
__device__ float g_thr[TT];

// ---------------- RMSNorm ----------------
__global__ void rmsnorm_kernel(const float* __restrict__ x,
                               const float* __restrict__ w,
                               float* __restrict__ out) {
    int row = blockIdx.x;
    const float4* x4 = (const float4*)(x + (size_t)row * HH);
    const float4* w4 = (const float4*)w;
    float s = 0.f;
    for (int i = threadIdx.x; i < HH / 4; i += 256) {
        float4 v = x4[i];
        s += v.x * v.x + v.y * v.y + v.z * v.z + v.w * v.w;
    }
    __shared__ float red[256];
    red[threadIdx.x] = s;
    __syncthreads();
    for (int o = 128; o > 0; o >>= 1) {
        if (threadIdx.x < o) red[threadIdx.x] += red[threadIdx.x + o];
        __syncthreads();
    }
    float rs = rsqrtf(red[0] / (float)HH + 1e-6f);
    float4* o4 = (float4*)(out + (size_t)row * HH);
    for (int i = threadIdx.x; i < HH / 4; i += 256) {
        float4 a = x4[i];
        float4 ww = w4[i];
        a.x = a.x * rs * ww.x;
        a.y = a.y * rs * ww.y;
        a.z = a.z * rs * ww.z;
        a.w = a.w * rs * ww.w;
        o4[i] = a;
    }
}

// ================= bf16 split mma GEMM, 512 threads, warp tile 32x32 =======
__device__ __forceinline__ uint32_t packbf(__nv_bfloat16 a, __nv_bfloat16 b) {
    __nv_bfloat162 t;
    t.x = a; t.y = b;
    return *(uint32_t*)&t;
}

__device__ __forceinline__ void split4(float4 v, uint2& hi, uint2& lo) {
    __nv_bfloat16 hx = __float2bfloat16(v.x);
    __nv_bfloat16 hy = __float2bfloat16(v.y);
    __nv_bfloat16 hz = __float2bfloat16(v.z);
    __nv_bfloat16 hw = __float2bfloat16(v.w);
    __nv_bfloat16 lx = __float2bfloat16(v.x - __bfloat162float(hx));
    __nv_bfloat16 ly = __float2bfloat16(v.y - __bfloat162float(hy));
    __nv_bfloat16 lz = __float2bfloat16(v.z - __bfloat162float(hz));
    __nv_bfloat16 lw = __float2bfloat16(v.w - __bfloat162float(hw));
    hi.x = packbf(hx, hy); hi.y = packbf(hz, hw);
    lo.x = packbf(lx, ly); lo.y = packbf(lz, lw);
}

__device__ __forceinline__ void mma16(float* c, uint32_t a0, uint32_t a1,
                                      uint32_t a2, uint32_t a3,
                                      uint32_t b0, uint32_t b1) {
    asm volatile(
        "mma.sync.aligned.m16n8k16.row.col.f32.bf16.bf16.f32 "
        "{%0,%1,%2,%3}, {%4,%5,%6,%7}, {%8,%9}, {%0,%1,%2,%3};"
        : "+f"(c[0]), "+f"(c[1]), "+f"(c[2]), "+f"(c[3])
        : "r"(a0), "r"(a1), "r"(a2), "r"(a3), "r"(b0), "r"(b1));
}

__device__ __forceinline__ void ldsm4(uint32_t addr, uint32_t& r0, uint32_t& r1,
                                      uint32_t& r2, uint32_t& r3) {
    asm volatile(
        "ldmatrix.sync.aligned.m8n8.x4.shared.b16 {%0,%1,%2,%3}, [%4];"
        : "=r"(r0), "=r"(r1), "=r"(r2), "=r"(r3) : "r"(addr));
}

__device__ __forceinline__ uint32_t smem_u32(const void* p) {
    uint32_t a;
    asm("{ .reg .u64 t; cvta.to.shared.u64 t, %1; cvt.u32.u64 %0, t; }"
        : "=r"(a) : "l"(p));
    return a;
}

#define STRH 40
#define HBUF (128 * STRH)

template <int NT>
__global__ void __launch_bounds__(512) bf16gemm_nt(
    const float* __restrict__ A, const float* __restrict__ B,
    const float* __restrict__ bias, const float* __restrict__ addsrc,
    float* __restrict__ C, int M, int N, int K) {
    extern __shared__ __nv_bfloat16 sh[];
    __nv_bfloat16* Ah = sh;
    __nv_bfloat16* Al = sh + 2 * HBUF;
    __nv_bfloat16* Bh = sh + 4 * HBUF;
    __nv_bfloat16* Bl = sh + 6 * HBUF;
    const uint32_t shU = smem_u32(sh);

    const int tid = threadIdx.x;
    const int lane = tid & 31;
    const int warp = tid >> 5;       // 0..15
    const int wm = warp & 3;         // 32-row quarter
    const int wn = warp >> 2;        // 32-col quarter
    const int bm = blockIdx.y * 128;
    const int bn = blockIdx.x * 128;

    const uint32_t arow = (uint32_t)(lane & 15) * STRH + (uint32_t)(lane >> 4) * 8;
    const uint32_t brow = (uint32_t)(8 * (lane >> 4) + (lane & 7)) * STRH +
                          (uint32_t)((lane >> 3) & 1) * 8;

    float acc[2][4][4];
#pragma unroll
    for (int i = 0; i < 2; i++)
#pragma unroll
        for (int j = 0; j < 4; j++)
#pragma unroll
            for (int l = 0; l < 4; l++) acc[i][j][l] = 0.f;

    const int lrow = tid >> 2;        // 0..127
    const int lc4 = (tid & 3) * 8;    // 0,8,16,24
    const float* Ag = A + (size_t)(bm + lrow) * K + lc4;
    const float* Bg = B + (size_t)(bn + lrow) * K + lc4;

    float4 pa[2], pb[2];
#pragma unroll
    for (int p = 0; p < 2; p++) {
        pa[p] = *(const float4*)(Ag + p * 4);
        pb[p] = *(const float4*)(Bg + p * 4);
    }

    const int NKT = K / 32;

#pragma unroll
    for (int p = 0; p < 2; p++) {
        uint2 hi, lo;
        split4(pa[p], hi, lo);
        *(uint2*)(Ah + lrow * STRH + lc4 + p * 4) = hi;
        *(uint2*)(Al + lrow * STRH + lc4 + p * 4) = lo;
        split4(pb[p], hi, lo);
        *(uint2*)(Bh + lrow * STRH + lc4 + p * 4) = hi;
        *(uint2*)(Bl + lrow * STRH + lc4 + p * 4) = lo;
    }
    __syncthreads();

    for (int kt = 0; kt < NKT; kt++) {
        const int cur = kt & 1;
        const bool more = (kt + 1 < NKT);
        if (more) {
            size_t off = (size_t)(kt + 1) * 32;
#pragma unroll
            for (int p = 0; p < 2; p++) {
                pa[p] = *(const float4*)(Ag + off + p * 4);
                pb[p] = *(const float4*)(Bg + off + p * 4);
            }
        }
        const uint32_t AhU = shU + 2u * (cur * HBUF);
        const uint32_t AlU = shU + 2u * (2 * HBUF + cur * HBUF);
        const uint32_t BhU = shU + 2u * (4 * HBUF + cur * HBUF);
        const uint32_t BlU = shU + 2u * (6 * HBUF + cur * HBUF);

#pragma unroll
        for (int ks = 0; ks < 2; ks++) {
            const uint32_t k = ks * 16;
            uint32_t afh[2][4], afl[2][4], bfh[4][2], bfl[4][2];
#pragma unroll
            for (int mi = 0; mi < 2; mi++) {
                uint32_t ro = (uint32_t)(wm * 32 + mi * 16) * STRH + arow + k;
                ldsm4(AhU + 2u * ro, afh[mi][0], afh[mi][1], afh[mi][2],
                      afh[mi][3]);
                ldsm4(AlU + 2u * ro, afl[mi][0], afl[mi][1], afl[mi][2],
                      afl[mi][3]);
            }
#pragma unroll
            for (int p = 0; p < 2; p++) {
                uint32_t ro = (uint32_t)(wn * 32 + p * 16) * STRH + brow + k;
                ldsm4(BhU + 2u * ro, bfh[2 * p][0], bfh[2 * p][1],
                      bfh[2 * p + 1][0], bfh[2 * p + 1][1]);
                ldsm4(BlU + 2u * ro, bfl[2 * p][0], bfl[2 * p][1],
                      bfl[2 * p + 1][0], bfl[2 * p + 1][1]);
            }
            // per-accumulator term order (hh,hl,lh,ll) unchanged -> bitwise
            // identical results vs R12/R13.
#pragma unroll
            for (int mi = 0; mi < 2; mi++)
#pragma unroll
                for (int ni = 0; ni < 4; ni++)
                    mma16(acc[mi][ni], afh[mi][0], afh[mi][1], afh[mi][2],
                          afh[mi][3], bfh[ni][0], bfh[ni][1]);
#pragma unroll
            for (int mi = 0; mi < 2; mi++)
#pragma unroll
                for (int ni = 0; ni < 4; ni++)
                    mma16(acc[mi][ni], afh[mi][0], afh[mi][1], afh[mi][2],
                          afh[mi][3], bfl[ni][0], bfl[ni][1]);
#pragma unroll
            for (int mi = 0; mi < 2; mi++)
#pragma unroll
                for (int ni = 0; ni < 4; ni++)
                    mma16(acc[mi][ni], afl[mi][0], afl[mi][1], afl[mi][2],
                          afl[mi][3], bfh[ni][0], bfh[ni][1]);
            if (NT == 4) {
#pragma unroll
                for (int mi = 0; mi < 2; mi++)
#pragma unroll
                    for (int ni = 0; ni < 4; ni++)
                        mma16(acc[mi][ni], afl[mi][0], afl[mi][1], afl[mi][2],
                              afl[mi][3], bfl[ni][0], bfl[ni][1]);
            }
        }

        if (more) {
            const int nxt = (kt + 1) & 1;
            __nv_bfloat16* Adh = Ah + nxt * HBUF;
            __nv_bfloat16* Adl = Al + nxt * HBUF;
            __nv_bfloat16* Bdh = Bh + nxt * HBUF;
            __nv_bfloat16* Bdl = Bl + nxt * HBUF;
#pragma unroll
            for (int p = 0; p < 2; p++) {
                uint2 hi, lo;
                split4(pa[p], hi, lo);
                *(uint2*)(Adh + lrow * STRH + lc4 + p * 4) = hi;
                *(uint2*)(Adl + lrow * STRH + lc4 + p * 4) = lo;
                split4(pb[p], hi, lo);
                *(uint2*)(Bdh + lrow * STRH + lc4 + p * 4) = hi;
                *(uint2*)(Bdl + lrow * STRH + lc4 + p * 4) = lo;
            }
        }
        __syncthreads();
    }

    const int g = lane >> 2;
    const int tg = lane & 3;
#pragma unroll
    for (int mi = 0; mi < 2; mi++) {
        int r0 = bm + wm * 32 + mi * 16 + g;
#pragma unroll
        for (int ni = 0; ni < 4; ni++) {
            int col = bn + wn * 32 + ni * 8 + tg * 2;
            float2 v0, v1;
            v0.x = acc[mi][ni][0]; v0.y = acc[mi][ni][1];
            v1.x = acc[mi][ni][2]; v1.y = acc[mi][ni][3];
            if (bias) {
                float2 bb = *(const float2*)(bias + col);
                v0.x += bb.x; v0.y += bb.y;
                v1.x += bb.x; v1.y += bb.y;
            }
            size_t i0 = (size_t)r0 * N + col;
            size_t i1 = (size_t)(r0 + 8) * N + col;
            if (addsrc) {
                float2 s0 = *(const float2*)(addsrc + i0);
                float2 s1 = *(const float2*)(addsrc + i1);
                v0.x += s0.x; v0.y += s0.y;
                v1.x += s1.x; v1.y += s1.y;
            }
            *(float2*)(C + i0) = v0;
            *(float2*)(C + i1) = v1;
        }
    }
}

// ---------------- RoPE (position_ids int32) ----------------
__global__ void rope_kernel(float* __restrict__ q, float* __restrict__ k,
                            const int* __restrict__ pos) {
    int idx = blockIdx.x * 256 + threadIdx.x;
    if (idx >= TT * NH * 64) return;
    int j = idx & 63;
    int th = idx >> 6;
    int t = th >> 5;
    float p = (float)pos[t];
    float ang = p * exp2f(-(float)j * (13.287712379549449f / 64.f));
    float s, c;
    sincosf(ang, &s, &c);
    size_t base = (size_t)th * HD + j;
    float q0 = q[base], q1 = q[base + 64];
    q[base] = q0 * c - q1 * s;
    q[base + 64] = q1 * c + q0 * s;
    float k0 = k[base], k1 = k[base + 64];
    k[base] = k0 * c - k1 * s;
    k[base + 64] = k1 * c + k0 * s;
}

// ---------------- attn predictor logits (exact; reads exact ln1-hs) --------
__global__ void attn_pred_kernel(const float* __restrict__ hs,
                                 const float* __restrict__ w,
                                 const float* __restrict__ b,
                                 float* __restrict__ out) {
    int t = blockIdx.x;
    int warp = threadIdx.x >> 5, lane = threadIdx.x & 31;
    const float* hsrow = hs + (size_t)t * HH;
    for (int hh = 0; hh < 4; hh++) {
        int h = warp * 4 + hh;
        const float* wr = w + (size_t)h * HH;
        float s = 0.f;
        for (int kk = lane; kk < HH; kk += 32) s += hsrow[kk] * wr[kk];
        for (int o = 16; o > 0; o >>= 1) s += __shfl_xor_sync(0xffffffffu, s, o);
        if (lane == 0) out[t * NH + h] = s + b[h];
    }
}

// ---------------- head top-16 mask ----------------
__global__ void head_mask_kernel(const float* __restrict__ logit,
                                 float* __restrict__ mask) {
    int t = blockIdx.x;
    int h = threadIdx.x;
    float v = logit[t * NH + h];
    int rank = 0;
    for (int j = 0; j < NH; j++) {
        float vj = logit[t * NH + j];
        rank += (vj > v) || (vj == v && j < h);
    }
    mask[t * NH + h] = (rank < ATTN_TOPK) ? 1.f : 0.f;
}

// ---------------- attention: 8 q-rows per block, two-pass softmax ----------
__global__ void __launch_bounds__(128)
attention8_kernel(const float* __restrict__ q, const float* __restrict__ k,
                  const float* __restrict__ v, const float* __restrict__ hmask,
                  const int* __restrict__ amask, float* __restrict__ out) {
    extern __shared__ float asm_[];
    float* qs = asm_;                 // QB*HD
    float* P = asm_ + QB * HD;        // TT*QB
    __shared__ float red[128];
    const int t0 = blockIdx.x * QB;
    const int h = blockIdx.y;
    const int tid = threadIdx.x;
    const float NEGF = -3.4e38f;

    float act[QB];
    bool anyact = false;
#pragma unroll
    for (int r = 0; r < QB; r++) {
        act[r] = hmask[(t0 + r) * NH + h];
        anyact |= (act[r] != 0.f);
    }
    if (!anyact) {
#pragma unroll
        for (int r = 0; r < QB; r++)
            out[(size_t)(t0 + r) * HH + h * HD + tid] = 0.f;
        return;
    }
#pragma unroll
    for (int r = 0; r < QB; r++)
        qs[r * HD + tid] = q[(size_t)(t0 + r) * HH + h * HD + tid] *
                           0.08838834764831845f;
    __syncthreads();

    const int nk = t0 + QB;
    float lm[QB];
#pragma unroll
    for (int r = 0; r < QB; r++) lm[r] = NEGF;

    for (int j = tid; j < nk; j += 128) {
        float s[QB];
#pragma unroll
        for (int r = 0; r < QB; r++) s[r] = 0.f;
        bool am = (amask[j] != 0);
        if (am) {
            const float4* kr = (const float4*)(k + (size_t)j * HH + h * HD);
#pragma unroll
            for (int d4 = 0; d4 < 32; d4++) {
                float4 kv = kr[d4];
#pragma unroll
                for (int r = 0; r < QB; r++) {
                    float4 qv = *(const float4*)(qs + r * HD + d4 * 4);
                    s[r] += qv.x * kv.x + qv.y * kv.y + qv.z * kv.z +
                            qv.w * kv.w;
                }
            }
        }
        float val[QB];
#pragma unroll
        for (int r = 0; r < QB; r++) {
            val[r] = (am && j <= t0 + r) ? s[r] : NEGF;
            lm[r] = fmaxf(lm[r], val[r]);
        }
        float4 o0, o1;
        o0.x = val[0]; o0.y = val[1]; o0.z = val[2]; o0.w = val[3];
        o1.x = val[4]; o1.y = val[5]; o1.z = val[6]; o1.w = val[7];
        ((float4*)(P + j * QB))[0] = o0;
        ((float4*)(P + j * QB))[1] = o1;
    }
    float M[QB];
#pragma unroll
    for (int r = 0; r < QB; r++) {
        red[tid] = lm[r];
        __syncthreads();
        for (int o = 64; o > 0; o >>= 1) {
            if (tid < o) red[tid] = fmaxf(red[tid], red[tid + o]);
            __syncthreads();
        }
        M[r] = red[0];
        __syncthreads();
    }
    float ls[QB];
#pragma unroll
    for (int r = 0; r < QB; r++) ls[r] = 0.f;
    for (int j = tid; j < nk; j += 128) {
        float4 a = ((float4*)(P + j * QB))[0];
        float4 b = ((float4*)(P + j * QB))[1];
        a.x = __expf(a.x - M[0]); a.y = __expf(a.y - M[1]);
        a.z = __expf(a.z - M[2]); a.w = __expf(a.w - M[3]);
        b.x = __expf(b.x - M[4]); b.y = __expf(b.y - M[5]);
        b.z = __expf(b.z - M[6]); b.w = __expf(b.w - M[7]);
        ls[0] += a.x; ls[1] += a.y; ls[2] += a.z; ls[3] += a.w;
        ls[4] += b.x; ls[5] += b.y; ls[6] += b.z; ls[7] += b.w;
        ((float4*)(P + j * QB))[0] = a;
        ((float4*)(P + j * QB))[1] = b;
    }
    float inv[QB];
#pragma unroll
    for (int r = 0; r < QB; r++) {
        red[tid] = ls[r];
        __syncthreads();
        for (int o = 64; o > 0; o >>= 1) {
            if (tid < o) red[tid] += red[tid + o];
            __syncthreads();
        }
        inv[r] = 1.f / red[0];
        __syncthreads();
    }
    float acc[QB];
#pragma unroll
    for (int r = 0; r < QB; r++) acc[r] = 0.f;
#pragma unroll 4
    for (int j = 0; j < nk; j++) {
        float vv = v[(size_t)j * HH + h * HD + tid];
        float4 a = ((float4*)(P + j * QB))[0];
        float4 b = ((float4*)(P + j * QB))[1];
        acc[0] = fmaf(a.x, vv, acc[0]); acc[1] = fmaf(a.y, vv, acc[1]);
        acc[2] = fmaf(a.z, vv, acc[2]); acc[3] = fmaf(a.w, vv, acc[3]);
        acc[4] = fmaf(b.x, vv, acc[4]); acc[5] = fmaf(b.y, vv, acc[5]);
        acc[6] = fmaf(b.z, vv, acc[6]); acc[7] = fmaf(b.w, vv, acc[7]);
    }
#pragma unroll
    for (int r = 0; r < QB; r++)
        out[(size_t)(t0 + r) * HH + h * HD + tid] =
            (act[r] != 0.f) ? acc[r] * inv[r] : 0.f;
}

// ---------------- top-k radix select machinery ----------------
__device__ __forceinline__ unsigned fkey(float x) {
    unsigned b = __float_as_uint(x);
    return (b & 0x80000000u) ? ~b : (b | 0x80000000u);
}
__device__ __forceinline__ float unfkey(unsigned k) {
    unsigned b = (k & 0x80000000u) ? (k & 0x7fffffffu) : ~k;
    return __uint_as_float(b);
}

__global__ void mlp_thresh_kernel(const float* __restrict__ logits,
                                  float* __restrict__ thr) {
    int row = blockIdx.x;
    const float* lr = logits + (size_t)row * II;
    __shared__ unsigned hist[256];
    __shared__ unsigned sh_sel, sh_kk;
    int tid = threadIdx.x;
    unsigned prefix = 0;
    unsigned kk = MLP_TOPK;
    for (int shift = 24; shift >= 0; shift -= 8) {
        hist[tid] = 0;
        __syncthreads();
        for (int i = tid; i < II; i += 256) {
            unsigned u = fkey(lr[i]);
            bool ok = (shift == 24) || ((u >> (shift + 8)) == prefix);
            if (ok) atomicAdd(&hist[(u >> shift) & 255u], 1u);
        }
        __syncthreads();
        if (tid == 0) {
            unsigned c = 0;
            int sel = 0;
            for (int b = 255; b >= 0; b--) {
                c += hist[b];
                if (c >= kk) { sel = b; break; }
            }
            sh_sel = (unsigned)sel;
            sh_kk = kk - (c - hist[sel]);
        }
        __syncthreads();
        prefix = (prefix << 8) | sh_sel;
        kk = sh_kk;
        __syncthreads();
    }
    if (tid == 0) thr[row] = unfkey(prefix);
}

#define BAND 4e-3f
__global__ void mlp_correct_kernel(float* __restrict__ mlog,
                                   const float* __restrict__ hs,
                                   const float* __restrict__ w,
                                   const float* __restrict__ b,
                                   const float* __restrict__ thr) {
    int row = blockIdx.x;
    int tid = threadIdx.x;
    __shared__ int cnt;
    __shared__ int idxs[1024];
    if (tid == 0) cnt = 0;
    __syncthreads();
    float th = thr[row];
    float* lr = mlog + (size_t)row * II;
    for (int i = tid; i < II; i += 256) {
        if (fabsf(lr[i] - th) <= BAND) {
            int p = atomicAdd(&cnt, 1);
            if (p < 1024) idxs[p] = i;
        }
    }
    __syncthreads();
    int n = cnt < 1024 ? cnt : 1024;
    int warp = tid >> 5, lane = tid & 31;
    const float* hsr = hs + (size_t)row * HH;
    for (int c = warp; c < n; c += 8) {
        int i = idxs[c];
        const float* wr = w + (size_t)i * HH;
        float s = 0.f;
        for (int kk = lane; kk < HH; kk += 32) s += hsr[kk] * wr[kk];
        for (int o = 16; o > 0; o >>= 1) s += __shfl_xor_sync(0xffffffffu, s, o);
        if (lane == 0) lr[i] = s + b[i];
    }
}

__global__ void mlp_topk_kernel(const float* __restrict__ logits,
                                float* __restrict__ mask) {
    int row = blockIdx.x;
    const float* lr = logits + (size_t)row * II;
    __shared__ unsigned hist[256];
    __shared__ unsigned sh_sel, sh_kk;
    __shared__ unsigned sh_cnt[2];
    int tid = threadIdx.x;
    unsigned prefix = 0;
    unsigned kk = MLP_TOPK;
    for (int shift = 24; shift >= 0; shift -= 8) {
        hist[tid] = 0;
        __syncthreads();
        for (int i = tid; i < II; i += 256) {
            unsigned u = fkey(lr[i]);
            bool ok = (shift == 24) || ((u >> (shift + 8)) == prefix);
            if (ok) atomicAdd(&hist[(u >> shift) & 255u], 1u);
        }
        __syncthreads();
        if (tid == 0) {
            unsigned c = 0;
            int sel = 0;
            for (int b = 255; b >= 0; b--) {
                c += hist[b];
                if (c >= kk) { sel = b; break; }
            }
            sh_sel = (unsigned)sel;
            sh_kk = kk - (c - hist[sel]);
        }
        __syncthreads();
        prefix = (prefix << 8) | sh_sel;
        kk = sh_kk;
        __syncthreads();
    }
    unsigned thresh = prefix;
    if (tid < 2) sh_cnt[tid] = 0;
    __syncthreads();
    unsigned lg = 0, le = 0;
    for (int i = tid; i < II; i += 256) {
        unsigned u = fkey(lr[i]);
        if (u > thresh) lg++;
        else if (u == thresh) le++;
    }
    atomicAdd(&sh_cnt[0], lg);
    atomicAdd(&sh_cnt[1], le);
    __syncthreads();
    unsigned g = sh_cnt[0], e = sh_cnt[1];
    float* mr = mask + (size_t)row * II;
    if (g + e == MLP_TOPK) {
        for (int i = tid; i < II; i += 256)
            mr[i] = (fkey(lr[i]) >= thresh) ? 1.f : 0.f;
    } else {
        for (int i = tid; i < II; i += 256)
            mr[i] = (fkey(lr[i]) > thresh) ? 1.f : 0.f;
        __syncthreads();
        if (tid == 0) {
            unsigned quota = MLP_TOPK - g;
            for (int i = 0; i < II && quota > 0; i++) {
                if (fkey(lr[i]) == thresh) { mr[i] = 1.f; quota--; }
            }
        }
    }
}

// ---------------- silu * up * mask ----------------
__global__ void silu_mul_mask_kernel(float* __restrict__ gate,
                                     const float* __restrict__ up,
                                     const float* __restrict__ mask, int n) {
    int i = blockIdx.x * 256 + threadIdx.x;
    if (i < n) {
        float x = gate[i];
        float si = x / (1.f + __expf(-x));
        gate[i] = si * up[i] * mask[i];
    }
}

// ---------------- launch ----------------
extern "C" void kernel_launch(void* const* d_in, const int* in_sizes, int n_in,
                              void* d_out, int out_size) {
    const float* hidden = (const float*)d_in[0];
    const int* amask = (const int*)d_in[1];
    const int* pos = (const int*)d_in[2];
    const float* wq = (const float*)d_in[3];
    const float* wk = (const float*)d_in[4];
    const float* wv = (const float*)d_in[5];
    const float* wo = (const float*)d_in[6];
    const float* w_gate = (const float*)d_in[7];
    const float* w_up = (const float*)d_in[8];
    const float* w_down = (const float*)d_in[9];
    const float* ln1 = (const float*)d_in[10];
    const float* ln2 = (const float*)d_in[11];
    const float* apw = (const float*)d_in[12];
    const float* apb = (const float*)d_in[13];
    const float* mpw = (const float*)d_in[14];
    const float* mpb = (const float*)d_in[15];
    float* out = (float*)d_out;

    float *hs, *q, *k, *v, *attn, *res2, *hlog, *hmask, *mlog, *fcm, *gate, *up,
        *thr;
    cudaGetSymbolAddress((void**)&hs, g_hs);
    cudaGetSymbolAddress((void**)&q, g_q);
    cudaGetSymbolAddress((void**)&k, g_k);
    cudaGetSymbolAddress((void**)&v, g_v);
    cudaGetSymbolAddress((void**)&attn, g_attn);
    cudaGetSymbolAddress((void**)&res2, g_res2);
    cudaGetSymbolAddress((void**)&hlog, g_hlogit);
    cudaGetSymbolAddress((void**)&hmask, g_headmask);
    cudaGetSymbolAddress((void**)&mlog, g_mlogit);
    cudaGetSymbolAddress((void**)&fcm, g_fcmask);
    cudaGetSymbolAddress((void**)&gate, g_gate);
    cudaGetSymbolAddress((void**)&up, g_up);
    cudaGetSymbolAddress((void**)&thr, g_thr);

    const int SMEM_B = 8 * HBUF * (int)sizeof(__nv_bfloat16);   // 81920 B
    cudaFuncSetAttribute(bf16gemm_nt<3>,
                         cudaFuncAttributeMaxDynamicSharedMemorySize, SMEM_B);
    cudaFuncSetAttribute(bf16gemm_nt<4>,
                         cudaFuncAttributeMaxDynamicSharedMemorySize, SMEM_B);
    const int SMEM_A = (QB * HD + TT * QB) * (int)sizeof(float);  // 69632 B
    cudaFuncSetAttribute(attention8_kernel,
                         cudaFuncAttributeMaxDynamicSharedMemorySize, SMEM_A);

    dim3 gHH(HH / 128, TT / 128);
    dim3 gII(II / 128, TT / 128);

    rmsnorm_kernel<<<TT, 256>>>(hidden, ln1, hs);
    bf16gemm_nt<4><<<gHH, 512, SMEM_B>>>(hs, wq, nullptr, nullptr, q, TT, HH, HH);
    bf16gemm_nt<4><<<gHH, 512, SMEM_B>>>(hs, wk, nullptr, nullptr, k, TT, HH, HH);
    bf16gemm_nt<4><<<gHH, 512, SMEM_B>>>(hs, wv, nullptr, nullptr, v, TT, HH, HH);
    rope_kernel<<<(TT * NH * 64 + 255) / 256, 256>>>(q, k, pos);
    attn_pred_kernel<<<TT, 256>>>(hs, apw, apb, hlog);
    head_mask_kernel<<<TT, 32>>>(hlog, hmask);
    attention8_kernel<<<dim3(TT / QB, NH), 128, SMEM_A>>>(q, k, v, hmask, amask,
                                                          attn);
    bf16gemm_nt<4><<<gHH, 512, SMEM_B>>>(attn, wo, nullptr, hidden, res2, TT, HH, HH);
    rmsnorm_kernel<<<TT, 256>>>(res2, ln2, hs);
    bf16gemm_nt<3><<<gII, 512, SMEM_B>>>(hs, mpw, mpb, nullptr, mlog, TT, II, HH);
    mlp_thresh_kernel<<<TT, 256>>>(mlog, thr);
    mlp_correct_kernel<<<TT, 256>>>(mlog, hs, mpw, mpb, thr);
    mlp_topk_kernel<<<TT, 256>>>(mlog, fcm);
    bf16gemm_nt<3><<<gII, 512, SMEM_B>>>(hs, w_gate, nullptr, nullptr, gate, TT, II, HH);
    bf16gemm_nt<3><<<gII, 512, SMEM_B>>>(hs, w_up, nullptr, nullptr, up, TT, II, HH);
    silu_mul_mask_kernel<<<(TT * II + 255) / 256, 256>>>(gate, up, fcm, TT * II);
    bf16gemm_nt<3><<<gHH, 512, SMEM_B>>>(gate, w_down, nullptr, res2, out, TT, HH, II);
}

// round 15
// speedup vs baseline: 1.0425x; 1.0425x over previous
#include <cuda_runtime.h>
#include <cuda_bf16.h>
#include <math.h>
#include <stdint.h>

#define TT 2048
#define HH 4096
#define NH 32
#define HD 128
#define II 11008
#define ATTN_TOPK 16
#define MLP_TOPK 2048
#define QB 8

// ---------------- scratch ----------------
__device__ float g_hs[TT * HH];
__device__ float g_q[TT * HH];
__device__ float g_k[TT * HH];
__device__ float g_v[TT * HH];
__device__ float g_attn[TT * HH];
__device__ float g_res2[TT * HH];
__device__ float g_hlogit[TT * NH];
__device__ float g_headmask[TT * NH];
__device__ float g_mlogit[TT * II];
__device__ float g_fcmask[TT * II];
__device__ float g_gate[TT * II];
__device__ float g_up[TT * II];
__device__ float g_thr[TT];

// ---------------- RMSNorm ----------------
__global__ void rmsnorm_kernel(const float* __restrict__ x,
                               const float* __restrict__ w,
                               float* __restrict__ out) {
    int row = blockIdx.x;
    const float4* x4 = (const float4*)(x + (size_t)row * HH);
    const float4* w4 = (const float4*)w;
    float s = 0.f;
    for (int i = threadIdx.x; i < HH / 4; i += 256) {
        float4 v = x4[i];
        s += v.x * v.x + v.y * v.y + v.z * v.z + v.w * v.w;
    }
    __shared__ float red[256];
    red[threadIdx.x] = s;
    __syncthreads();
    for (int o = 128; o > 0; o >>= 1) {
        if (threadIdx.x < o) red[threadIdx.x] += red[threadIdx.x + o];
        __syncthreads();
    }
    float rs = rsqrtf(red[0] / (float)HH + 1e-6f);
    float4* o4 = (float4*)(out + (size_t)row * HH);
    for (int i = threadIdx.x; i < HH / 4; i += 256) {
        float4 a = x4[i];
        float4 ww = w4[i];
        a.x = a.x * rs * ww.x;
        a.y = a.y * rs * ww.y;
        a.z = a.z * rs * ww.z;
        a.w = a.w * rs * ww.w;
        o4[i] = a;
    }
}

// ================= bf16x3 mma GEMM, 512 threads, warp tile 32x32 ===========
__device__ __forceinline__ uint32_t packbf(__nv_bfloat16 a, __nv_bfloat16 b) {
    __nv_bfloat162 t;
    t.x = a; t.y = b;
    return *(uint32_t*)&t;
}

__device__ __forceinline__ void split4(float4 v, uint2& hi, uint2& lo) {
    __nv_bfloat16 hx = __float2bfloat16(v.x);
    __nv_bfloat16 hy = __float2bfloat16(v.y);
    __nv_bfloat16 hz = __float2bfloat16(v.z);
    __nv_bfloat16 hw = __float2bfloat16(v.w);
    __nv_bfloat16 lx = __float2bfloat16(v.x - __bfloat162float(hx));
    __nv_bfloat16 ly = __float2bfloat16(v.y - __bfloat162float(hy));
    __nv_bfloat16 lz = __float2bfloat16(v.z - __bfloat162float(hz));
    __nv_bfloat16 lw = __float2bfloat16(v.w - __bfloat162float(hw));
    hi.x = packbf(hx, hy); hi.y = packbf(hz, hw);
    lo.x = packbf(lx, ly); lo.y = packbf(lz, lw);
}

__device__ __forceinline__ void mma16(float* c, uint32_t a0, uint32_t a1,
                                      uint32_t a2, uint32_t a3,
                                      uint32_t b0, uint32_t b1) {
    asm volatile(
        "mma.sync.aligned.m16n8k16.row.col.f32.bf16.bf16.f32 "
        "{%0,%1,%2,%3}, {%4,%5,%6,%7}, {%8,%9}, {%0,%1,%2,%3};"
        : "+f"(c[0]), "+f"(c[1]), "+f"(c[2]), "+f"(c[3])
        : "r"(a0), "r"(a1), "r"(a2), "r"(a3), "r"(b0), "r"(b1));
}

__device__ __forceinline__ void ldsm4(uint32_t addr, uint32_t& r0, uint32_t& r1,
                                      uint32_t& r2, uint32_t& r3) {
    asm volatile(
        "ldmatrix.sync.aligned.m8n8.x4.shared.b16 {%0,%1,%2,%3}, [%4];"
        : "=r"(r0), "=r"(r1), "=r"(r2), "=r"(r3) : "r"(addr));
}

__device__ __forceinline__ uint32_t smem_u32(const void* p) {
    uint32_t a;
    asm("{ .reg .u64 t; cvta.to.shared.u64 t, %1; cvt.u32.u64 %0, t; }"
        : "=r"(a) : "l"(p));
    return a;
}

#define STRH 40
#define HBUF (128 * STRH)

__global__ void __launch_bounds__(512) bf16gemm_nt(
    const float* __restrict__ A, const float* __restrict__ B,
    const float* __restrict__ bias, const float* __restrict__ addsrc,
    float* __restrict__ C, int M, int N, int K) {
    extern __shared__ __nv_bfloat16 sh[];
    __nv_bfloat16* Ah = sh;
    __nv_bfloat16* Al = sh + 2 * HBUF;
    __nv_bfloat16* Bh = sh + 4 * HBUF;
    __nv_bfloat16* Bl = sh + 6 * HBUF;
    const uint32_t shU = smem_u32(sh);

    const int tid = threadIdx.x;
    const int lane = tid & 31;
    const int warp = tid >> 5;
    const int wm = warp & 3;
    const int wn = warp >> 2;
    const int bm = blockIdx.y * 128;
    const int bn = blockIdx.x * 128;

    const uint32_t arow = (uint32_t)(lane & 15) * STRH + (uint32_t)(lane >> 4) * 8;
    const uint32_t brow = (uint32_t)(8 * (lane >> 4) + (lane & 7)) * STRH +
                          (uint32_t)((lane >> 3) & 1) * 8;

    float acc[2][4][4];
#pragma unroll
    for (int i = 0; i < 2; i++)
#pragma unroll
        for (int j = 0; j < 4; j++)
#pragma unroll
            for (int l = 0; l < 4; l++) acc[i][j][l] = 0.f;

    const int lrow = tid >> 2;
    const int lc4 = (tid & 3) * 8;
    const float* Ag = A + (size_t)(bm + lrow) * K + lc4;
    const float* Bg = B + (size_t)(bn + lrow) * K + lc4;

    float4 pa[2], pb[2];
#pragma unroll
    for (int p = 0; p < 2; p++) {
        pa[p] = *(const float4*)(Ag + p * 4);
        pb[p] = *(const float4*)(Bg + p * 4);
    }

    const int NKT = K / 32;

#pragma unroll
    for (int p = 0; p < 2; p++) {
        uint2 hi, lo;
        split4(pa[p], hi, lo);
        *(uint2*)(Ah + lrow * STRH + lc4 + p * 4) = hi;
        *(uint2*)(Al + lrow * STRH + lc4 + p * 4) = lo;
        split4(pb[p], hi, lo);
        *(uint2*)(Bh + lrow * STRH + lc4 + p * 4) = hi;
        *(uint2*)(Bl + lrow * STRH + lc4 + p * 4) = lo;
    }
    __syncthreads();

    for (int kt = 0; kt < NKT; kt++) {
        const int cur = kt & 1;
        const bool more = (kt + 1 < NKT);
        if (more) {
            size_t off = (size_t)(kt + 1) * 32;
#pragma unroll
            for (int p = 0; p < 2; p++) {
                pa[p] = *(const float4*)(Ag + off + p * 4);
                pb[p] = *(const float4*)(Bg + off + p * 4);
            }
        }
        const uint32_t AhU = shU + 2u * (cur * HBUF);
        const uint32_t AlU = shU + 2u * (2 * HBUF + cur * HBUF);
        const uint32_t BhU = shU + 2u * (4 * HBUF + cur * HBUF);
        const uint32_t BlU = shU + 2u * (6 * HBUF + cur * HBUF);

#pragma unroll
        for (int ks = 0; ks < 2; ks++) {
            const uint32_t k = ks * 16;
            uint32_t afh[2][4], afl[2][4], bfh[4][2], bfl[4][2];
#pragma unroll
            for (int mi = 0; mi < 2; mi++) {
                uint32_t ro = (uint32_t)(wm * 32 + mi * 16) * STRH + arow + k;
                ldsm4(AhU + 2u * ro, afh[mi][0], afh[mi][1], afh[mi][2],
                      afh[mi][3]);
                ldsm4(AlU + 2u * ro, afl[mi][0], afl[mi][1], afl[mi][2],
                      afl[mi][3]);
            }
#pragma unroll
            for (int p = 0; p < 2; p++) {
                uint32_t ro = (uint32_t)(wn * 32 + p * 16) * STRH + brow + k;
                ldsm4(BhU + 2u * ro, bfh[2 * p][0], bfh[2 * p][1],
                      bfh[2 * p + 1][0], bfh[2 * p + 1][1]);
                ldsm4(BlU + 2u * ro, bfl[2 * p][0], bfl[2 * p][1],
                      bfl[2 * p + 1][0], bfl[2 * p + 1][1]);
            }
#pragma unroll
            for (int mi = 0; mi < 2; mi++)
#pragma unroll
                for (int ni = 0; ni < 4; ni++)
                    mma16(acc[mi][ni], afh[mi][0], afh[mi][1], afh[mi][2],
                          afh[mi][3], bfh[ni][0], bfh[ni][1]);
#pragma unroll
            for (int mi = 0; mi < 2; mi++)
#pragma unroll
                for (int ni = 0; ni < 4; ni++)
                    mma16(acc[mi][ni], afh[mi][0], afh[mi][1], afh[mi][2],
                          afh[mi][3], bfl[ni][0], bfl[ni][1]);
#pragma unroll
            for (int mi = 0; mi < 2; mi++)
#pragma unroll
                for (int ni = 0; ni < 4; ni++)
                    mma16(acc[mi][ni], afl[mi][0], afl[mi][1], afl[mi][2],
                          afl[mi][3], bfh[ni][0], bfh[ni][1]);
        }

        if (more) {
            const int nxt = (kt + 1) & 1;
            __nv_bfloat16* Adh = Ah + nxt * HBUF;
            __nv_bfloat16* Adl = Al + nxt * HBUF;
            __nv_bfloat16* Bdh = Bh + nxt * HBUF;
            __nv_bfloat16* Bdl = Bl + nxt * HBUF;
#pragma unroll
            for (int p = 0; p < 2; p++) {
                uint2 hi, lo;
                split4(pa[p], hi, lo);
                *(uint2*)(Adh + lrow * STRH + lc4 + p * 4) = hi;
                *(uint2*)(Adl + lrow * STRH + lc4 + p * 4) = lo;
                split4(pb[p], hi, lo);
                *(uint2*)(Bdh + lrow * STRH + lc4 + p * 4) = hi;
                *(uint2*)(Bdl + lrow * STRH + lc4 + p * 4) = lo;
            }
        }
        __syncthreads();
    }

    const int g = lane >> 2;
    const int tg = lane & 3;
#pragma unroll
    for (int mi = 0; mi < 2; mi++) {
        int r0 = bm + wm * 32 + mi * 16 + g;
#pragma unroll
        for (int ni = 0; ni < 4; ni++) {
            int col = bn + wn * 32 + ni * 8 + tg * 2;
            float2 v0, v1;
            v0.x = acc[mi][ni][0]; v0.y = acc[mi][ni][1];
            v1.x = acc[mi][ni][2]; v1.y = acc[mi][ni][3];
            if (bias) {
                float2 bb = *(const float2*)(bias + col);
                v0.x += bb.x; v0.y += bb.y;
                v1.x += bb.x; v1.y += bb.y;
            }
            size_t i0 = (size_t)r0 * N + col;
            size_t i1 = (size_t)(r0 + 8) * N + col;
            if (addsrc) {
                float2 s0 = *(const float2*)(addsrc + i0);
                float2 s1 = *(const float2*)(addsrc + i1);
                v0.x += s0.x; v0.y += s0.y;
                v1.x += s1.x; v1.y += s1.y;
            }
            *(float2*)(C + i0) = v0;
            *(float2*)(C + i1) = v1;
        }
    }
}

// ---------------- RoPE (position_ids int32) ----------------
__global__ void rope_kernel(float* __restrict__ q, float* __restrict__ k,
                            const int* __restrict__ pos) {
    int idx = blockIdx.x * 256 + threadIdx.x;
    if (idx >= TT * NH * 64) return;
    int j = idx & 63;
    int th = idx >> 6;
    int t = th >> 5;
    float p = (float)pos[t];
    float ang = p * exp2f(-(float)j * (13.287712379549449f / 64.f));
    float s, c;
    sincosf(ang, &s, &c);
    size_t base = (size_t)th * HD + j;
    float q0 = q[base], q1 = q[base + 64];
    q[base] = q0 * c - q1 * s;
    q[base + 64] = q1 * c + q0 * s;
    float k0 = k[base], k1 = k[base + 64];
    k[base] = k0 * c - k1 * s;
    k[base + 64] = k1 * c + k0 * s;
}

// ---------------- attn predictor logits ----------------
__global__ void attn_pred_kernel(const float* __restrict__ hs,
                                 const float* __restrict__ w,
                                 const float* __restrict__ b,
                                 float* __restrict__ out) {
    int t = blockIdx.x;
    int warp = threadIdx.x >> 5, lane = threadIdx.x & 31;
    const float* hsrow = hs + (size_t)t * HH;
    for (int hh = 0; hh < 4; hh++) {
        int h = warp * 4 + hh;
        const float* wr = w + (size_t)h * HH;
        float s = 0.f;
        for (int kk = lane; kk < HH; kk += 32) s += hsrow[kk] * wr[kk];
        for (int o = 16; o > 0; o >>= 1) s += __shfl_xor_sync(0xffffffffu, s, o);
        if (lane == 0) out[t * NH + h] = s + b[h];
    }
}

// ---------------- head top-16 mask ----------------
__global__ void head_mask_kernel(const float* __restrict__ logit,
                                 float* __restrict__ mask) {
    int t = blockIdx.x;
    int h = threadIdx.x;
    float v = logit[t * NH + h];
    int rank = 0;
    for (int j = 0; j < NH; j++) {
        float vj = logit[t * NH + j];
        rank += (vj > v) || (vj == v && j < h);
    }
    mask[t * NH + h] = (rank < ATTN_TOPK) ? 1.f : 0.f;
}

// ---------------- attention: compacted active rows, NR in {2,4,8} ----------
template <int NR>
__device__ __forceinline__ void attn_body(
    const float* __restrict__ q, const float* __restrict__ k,
    const float* __restrict__ v, const int* __restrict__ amask,
    float* __restrict__ out, float* qs, float* P, float* red,
    int t0, int h, int tid, int nact, const int* ridx) {
    const float NEGF = -3.4e38f;
    // compacted q load; pad slots with zeros
#pragma unroll
    for (int c = 0; c < NR; c++) {
        float val = 0.f;
        if (c < nact)
            val = q[(size_t)(t0 + ridx[c]) * HH + h * HD + tid] *
                  0.08838834764831845f;
        qs[c * HD + tid] = val;
    }
    __syncthreads();

    int jlim[NR];
#pragma unroll
    for (int c = 0; c < NR; c++) jlim[c] = (c < nact) ? (t0 + ridx[c]) : -1;
    const int nk = t0 + ridx[nact - 1] + 1;

    float lm[NR];
#pragma unroll
    for (int c = 0; c < NR; c++) lm[c] = NEGF;

    // pass1: scores
    for (int j = tid; j < nk; j += 128) {
        float s[NR];
#pragma unroll
        for (int c = 0; c < NR; c++) s[c] = 0.f;
        bool am = (amask[j] != 0);
        if (am) {
            const float4* kr = (const float4*)(k + (size_t)j * HH + h * HD);
#pragma unroll
            for (int d4 = 0; d4 < 32; d4++) {
                float4 kv = kr[d4];
#pragma unroll
                for (int c = 0; c < NR; c++) {
                    float4 qv = *(const float4*)(qs + c * HD + d4 * 4);
                    s[c] += qv.x * kv.x + qv.y * kv.y + qv.z * kv.z +
                            qv.w * kv.w;
                }
            }
        }
#pragma unroll
        for (int c = 0; c < NR; c++) {
            float vv = (am && j <= jlim[c]) ? s[c] : NEGF;
            s[c] = vv;
            lm[c] = fmaxf(lm[c], vv);
        }
        float* pj = P + j * NR;
        if (NR == 8) {
            float4 o0, o1;
            o0.x = s[0]; o0.y = s[1]; o0.z = s[2]; o0.w = s[3];
            o1.x = s[NR > 4 ? 4 : 0]; o1.y = s[NR > 4 ? 5 : 0];
            o1.z = s[NR > 4 ? 6 : 0]; o1.w = s[NR > 4 ? 7 : 0];
            ((float4*)pj)[0] = o0;
            ((float4*)pj)[1] = o1;
        } else if (NR == 4) {
            float4 o0;
            o0.x = s[0]; o0.y = s[1];
            o0.z = s[NR > 2 ? 2 : 0]; o0.w = s[NR > 2 ? 3 : 0];
            ((float4*)pj)[0] = o0;
        } else {
            float2 o0;
            o0.x = s[0]; o0.y = s[1];
            ((float2*)pj)[0] = o0;
        }
    }
    // row maxes
    float M[NR];
#pragma unroll
    for (int c = 0; c < NR; c++) {
        if (c >= nact) { M[c] = NEGF; continue; }
        red[tid] = lm[c];
        __syncthreads();
        for (int o = 64; o > 0; o >>= 1) {
            if (tid < o) red[tid] = fmaxf(red[tid], red[tid + o]);
            __syncthreads();
        }
        M[c] = red[0];
        __syncthreads();
    }
    // pass2: exp + sums
    float ls[NR];
#pragma unroll
    for (int c = 0; c < NR; c++) ls[c] = 0.f;
    for (int j = tid; j < nk; j += 128) {
        float* pj = P + j * NR;
        float e[NR];
#pragma unroll
        for (int c = 0; c < NR; c++) {
            float vv = (c < nact) ? __expf(pj[c] - M[c]) : 0.f;
            e[c] = vv;
            ls[c] += vv;
        }
#pragma unroll
        for (int c = 0; c < NR; c++) pj[c] = e[c];
    }
    float inv[NR];
#pragma unroll
    for (int c = 0; c < NR; c++) {
        if (c >= nact) { inv[c] = 0.f; continue; }
        red[tid] = ls[c];
        __syncthreads();
        for (int o = 64; o > 0; o >>= 1) {
            if (tid < o) red[tid] += red[tid + o];
            __syncthreads();
        }
        inv[c] = 1.f / red[0];
        __syncthreads();
    }
    // pass3: PV
    float acc[NR];
#pragma unroll
    for (int c = 0; c < NR; c++) acc[c] = 0.f;
#pragma unroll 4
    for (int j = 0; j < nk; j++) {
        float vv = v[(size_t)j * HH + h * HD + tid];
        const float* pj = P + j * NR;
#pragma unroll
        for (int c = 0; c < NR; c++) acc[c] = fmaf(pj[c], vv, acc[c]);
    }
#pragma unroll
    for (int c = 0; c < NR; c++) {
        if (c >= nact) break;
        out[(size_t)(t0 + ridx[c]) * HH + h * HD + tid] = acc[c] * inv[c];
    }
}

__global__ void __launch_bounds__(128)
attention8_kernel(const float* __restrict__ q, const float* __restrict__ k,
                  const float* __restrict__ v, const float* __restrict__ hmask,
                  const int* __restrict__ amask, float* __restrict__ out) {
    extern __shared__ float asm_[];
    float* qs = asm_;                 // QB*HD
    float* P = asm_ + QB * HD;        // TT*QB
    __shared__ float red[128];
    const int t0 = blockIdx.x * QB;
    const int h = blockIdx.y;
    const int tid = threadIdx.x;

    int ridx[QB];
    int nact = 0;
    float actv[QB];
#pragma unroll
    for (int r = 0; r < QB; r++) {
        actv[r] = hmask[(t0 + r) * NH + h];
        if (actv[r] != 0.f) ridx[nact++] = r;
    }
    // zero inactive rows
#pragma unroll
    for (int r = 0; r < QB; r++)
        if (actv[r] == 0.f)
            out[(size_t)(t0 + r) * HH + h * HD + tid] = 0.f;
    if (nact == 0) return;

    if (nact <= 2)
        attn_body<2>(q, k, v, amask, out, qs, P, red, t0, h, tid, nact, ridx);
    else if (nact <= 4)
        attn_body<4>(q, k, v, amask, out, qs, P, red, t0, h, tid, nact, ridx);
    else
        attn_body<8>(q, k, v, amask, out, qs, P, red, t0, h, tid, nact, ridx);
}

// ---------------- top-k radix select machinery ----------------
__device__ __forceinline__ unsigned fkey(float x) {
    unsigned b = __float_as_uint(x);
    return (b & 0x80000000u) ? ~b : (b | 0x80000000u);
}
__device__ __forceinline__ float unfkey(unsigned k) {
    unsigned b = (k & 0x80000000u) ? (k & 0x7fffffffu) : ~k;
    return __uint_as_float(b);
}

__global__ void mlp_thresh_kernel(const float* __restrict__ logits,
                                  float* __restrict__ thr) {
    int row = blockIdx.x;
    const float* lr = logits + (size_t)row * II;
    __shared__ unsigned hist[256];
    __shared__ unsigned sh_sel, sh_kk;
    int tid = threadIdx.x;
    unsigned prefix = 0;
    unsigned kk = MLP_TOPK;
    for (int shift = 24; shift >= 0; shift -= 8) {
        hist[tid] = 0;
        __syncthreads();
        for (int i = tid; i < II; i += 256) {
            unsigned u = fkey(lr[i]);
            bool ok = (shift == 24) || ((u >> (shift + 8)) == prefix);
            if (ok) atomicAdd(&hist[(u >> shift) & 255u], 1u);
        }
        __syncthreads();
        if (tid == 0) {
            unsigned c = 0;
            int sel = 0;
            for (int b = 255; b >= 0; b--) {
                c += hist[b];
                if (c >= kk) { sel = b; break; }
            }
            sh_sel = (unsigned)sel;
            sh_kk = kk - (c - hist[sel]);
        }
        __syncthreads();
        prefix = (prefix << 8) | sh_sel;
        kk = sh_kk;
        __syncthreads();
    }
    if (tid == 0) thr[row] = unfkey(prefix);
}

#define BAND 4e-3f
__global__ void mlp_correct_kernel(float* __restrict__ mlog,
                                   const float* __restrict__ hs,
                                   const float* __restrict__ w,
                                   const float* __restrict__ b,
                                   const float* __restrict__ thr) {
    int row = blockIdx.x;
    int tid = threadIdx.x;
    __shared__ int cnt;
    __shared__ int idxs[1024];
    if (tid == 0) cnt = 0;
    __syncthreads();
    float th = thr[row];
    float* lr = mlog + (size_t)row * II;
    for (int i = tid; i < II; i += 256) {
        if (fabsf(lr[i] - th) <= BAND) {
            int p = atomicAdd(&cnt, 1);
            if (p < 1024) idxs[p] = i;
        }
    }
    __syncthreads();
    int n = cnt < 1024 ? cnt : 1024;
    int warp = tid >> 5, lane = tid & 31;
    const float* hsr = hs + (size_t)row * HH;
    for (int c = warp; c < n; c += 8) {
        int i = idxs[c];
        const float* wr = w + (size_t)i * HH;
        float s = 0.f;
        for (int kk = lane; kk < HH; kk += 32) s += hsr[kk] * wr[kk];
        for (int o = 16; o > 0; o >>= 1) s += __shfl_xor_sync(0xffffffffu, s, o);
        if (lane == 0) lr[i] = s + b[i];
    }
}

__global__ void mlp_topk_kernel(const float* __restrict__ logits,
                                float* __restrict__ mask) {
    int row = blockIdx.x;
    const float* lr = logits + (size_t)row * II;
    __shared__ unsigned hist[256];
    __shared__ unsigned sh_sel, sh_kk;
    __shared__ unsigned sh_cnt[2];
    int tid = threadIdx.x;
    unsigned prefix = 0;
    unsigned kk = MLP_TOPK;
    for (int shift = 24; shift >= 0; shift -= 8) {
        hist[tid] = 0;
        __syncthreads();
        for (int i = tid; i < II; i += 256) {
            unsigned u = fkey(lr[i]);
            bool ok = (shift == 24) || ((u >> (shift + 8)) == prefix);
            if (ok) atomicAdd(&hist[(u >> shift) & 255u], 1u);
        }
        __syncthreads();
        if (tid == 0) {
            unsigned c = 0;
            int sel = 0;
            for (int b = 255; b >= 0; b--) {
                c += hist[b];
                if (c >= kk) { sel = b; break; }
            }
            sh_sel = (unsigned)sel;
            sh_kk = kk - (c - hist[sel]);
        }
        __syncthreads();
        prefix = (prefix << 8) | sh_sel;
        kk = sh_kk;
        __syncthreads();
    }
    unsigned thresh = prefix;
    if (tid < 2) sh_cnt[tid] = 0;
    __syncthreads();
    unsigned lg = 0, le = 0;
    for (int i = tid; i < II; i += 256) {
        unsigned u = fkey(lr[i]);
        if (u > thresh) lg++;
        else if (u == thresh) le++;
    }
    atomicAdd(&sh_cnt[0], lg);
    atomicAdd(&sh_cnt[1], le);
    __syncthreads();
    unsigned g = sh_cnt[0], e = sh_cnt[1];
    float* mr = mask + (size_t)row * II;
    if (g + e == MLP_TOPK) {
        for (int i = tid; i < II; i += 256)
            mr[i] = (fkey(lr[i]) >= thresh) ? 1.f : 0.f;
    } else {
        for (int i = tid; i < II; i += 256)
            mr[i] = (fkey(lr[i]) > thresh) ? 1.f : 0.f;
        __syncthreads();
        if (tid == 0) {
            unsigned quota = MLP_TOPK - g;
            for (int i = 0; i < II && quota > 0; i++) {
                if (fkey(lr[i]) == thresh) { mr[i] = 1.f; quota--; }
            }
        }
    }
}

// ---------------- silu * up * mask ----------------
__global__ void silu_mul_mask_kernel(float* __restrict__ gate,
                                     const float* __restrict__ up,
                                     const float* __restrict__ mask, int n) {
    int i = blockIdx.x * 256 + threadIdx.x;
    if (i < n) {
        float x = gate[i];
        float si = x / (1.f + __expf(-x));
        gate[i] = si * up[i] * mask[i];
    }
}

// ---------------- launch ----------------
extern "C" void kernel_launch(void* const* d_in, const int* in_sizes, int n_in,
                              void* d_out, int out_size) {
    const float* hidden = (const float*)d_in[0];
    const int* amask = (const int*)d_in[1];
    const int* pos = (const int*)d_in[2];
    const float* wq = (const float*)d_in[3];
    const float* wk = (const float*)d_in[4];
    const float* wv = (const float*)d_in[5];
    const float* wo = (const float*)d_in[6];
    const float* w_gate = (const float*)d_in[7];
    const float* w_up = (const float*)d_in[8];
    const float* w_down = (const float*)d_in[9];
    const float* ln1 = (const float*)d_in[10];
    const float* ln2 = (const float*)d_in[11];
    const float* apw = (const float*)d_in[12];
    const float* apb = (const float*)d_in[13];
    const float* mpw = (const float*)d_in[14];
    const float* mpb = (const float*)d_in[15];
    float* out = (float*)d_out;

    float *hs, *q, *k, *v, *attn, *res2, *hlog, *hmask, *mlog, *fcm, *gate, *up,
        *thr;
    cudaGetSymbolAddress((void**)&hs, g_hs);
    cudaGetSymbolAddress((void**)&q, g_q);
    cudaGetSymbolAddress((void**)&k, g_k);
    cudaGetSymbolAddress((void**)&v, g_v);
    cudaGetSymbolAddress((void**)&attn, g_attn);
    cudaGetSymbolAddress((void**)&res2, g_res2);
    cudaGetSymbolAddress((void**)&hlog, g_hlogit);
    cudaGetSymbolAddress((void**)&hmask, g_headmask);
    cudaGetSymbolAddress((void**)&mlog, g_mlogit);
    cudaGetSymbolAddress((void**)&fcm, g_fcmask);
    cudaGetSymbolAddress((void**)&gate, g_gate);
    cudaGetSymbolAddress((void**)&up, g_up);
    cudaGetSymbolAddress((void**)&thr, g_thr);

    const int SMEM_B = 8 * HBUF * (int)sizeof(__nv_bfloat16);   // 81920 B
    cudaFuncSetAttribute(bf16gemm_nt,
                         cudaFuncAttributeMaxDynamicSharedMemorySize, SMEM_B);
    const int SMEM_A = (QB * HD + TT * QB) * (int)sizeof(float);  // 69632 B
    cudaFuncSetAttribute(attention8_kernel,
                         cudaFuncAttributeMaxDynamicSharedMemorySize, SMEM_A);

    dim3 gHH(HH / 128, TT / 128);
    dim3 gII(II / 128, TT / 128);

    rmsnorm_kernel<<<TT, 256>>>(hidden, ln1, hs);
    bf16gemm_nt<<<gHH, 512, SMEM_B>>>(hs, wq, nullptr, nullptr, q, TT, HH, HH);
    bf16gemm_nt<<<gHH, 512, SMEM_B>>>(hs, wk, nullptr, nullptr, k, TT, HH, HH);
    bf16gemm_nt<<<gHH, 512, SMEM_B>>>(hs, wv, nullptr, nullptr, v, TT, HH, HH);
    rope_kernel<<<(TT * NH * 64 + 255) / 256, 256>>>(q, k, pos);
    attn_pred_kernel<<<TT, 256>>>(hs, apw, apb, hlog);
    head_mask_kernel<<<TT, 32>>>(hlog, hmask);
    attention8_kernel<<<dim3(TT / QB, NH), 128, SMEM_A>>>(q, k, v, hmask, amask,
                                                          attn);
    bf16gemm_nt<<<gHH, 512, SMEM_B>>>(attn, wo, nullptr, hidden, res2, TT, HH, HH);
    rmsnorm_kernel<<<TT, 256>>>(res2, ln2, hs);
    bf16gemm_nt<<<gII, 512, SMEM_B>>>(hs, mpw, mpb, nullptr, mlog, TT, II, HH);
    mlp_thresh_kernel<<<TT, 256>>>(mlog, thr);
    mlp_correct_kernel<<<TT, 256>>>(mlog, hs, mpw, mpb, thr);
    mlp_topk_kernel<<<TT, 256>>>(mlog, fcm);
    bf16gemm_nt<<<gII, 512, SMEM_B>>>(hs, w_gate, nullptr, nullptr, gate, TT, II, HH);
    bf16gemm_nt<<<gII, 512, SMEM_B>>>(hs, w_up, nullptr, nullptr, up, TT, II, HH);
    silu_mul_mask_kernel<<<(TT * II + 255) / 256, 256>>>(gate, up, fcm, TT * II);
    bf16gemm_nt<<<gHH, 512, SMEM_B>>>(gate, w_down, nullptr, res2, out, TT, HH, II);
}

// round 16
// speedup vs baseline: 1.1281x; 1.0821x over previous
#include <cuda_runtime.h>
#include <cuda_bf16.h>
#include <math.h>
#include <stdint.h>

#define TT 2048
#define HH 4096
#define NH 32
#define HD 128
#define II 11008
#define ATTN_TOPK 16
#define MLP_TOPK 2048
#define QB 8

// ---------------- scratch ----------------
__device__ float g_hs[TT * HH];
__device__ float g_q[TT * HH];
__device__ float g_k[TT * HH];
__device__ float g_v[TT * HH];
__device__ float g_attn[TT * HH];
__device__ float g_res2[TT * HH];
__device__ float g_hlogit[TT * NH];
__device__ float g_headmask[TT * NH];
__device__ float g_mlogit[TT * II];
__device__ float g_fcmask[TT * II];
__device__ float g_gate[TT * II];
__device__ float g_up[TT * II];
__device__ float g_thr[TT];

// ---------------- RMSNorm ----------------
__global__ void rmsnorm_kernel(const float* __restrict__ x,
                               const float* __restrict__ w,
                               float* __restrict__ out) {
    int row = blockIdx.x;
    const float4* x4 = (const float4*)(x + (size_t)row * HH);
    const float4* w4 = (const float4*)w;
    float s = 0.f;
    for (int i = threadIdx.x; i < HH / 4; i += 256) {
        float4 v = x4[i];
        s += v.x * v.x + v.y * v.y + v.z * v.z + v.w * v.w;
    }
    __shared__ float red[256];
    red[threadIdx.x] = s;
    __syncthreads();
    for (int o = 128; o > 0; o >>= 1) {
        if (threadIdx.x < o) red[threadIdx.x] += red[threadIdx.x + o];
        __syncthreads();
    }
    float rs = rsqrtf(red[0] / (float)HH + 1e-6f);
    float4* o4 = (float4*)(out + (size_t)row * HH);
    for (int i = threadIdx.x; i < HH / 4; i += 256) {
        float4 a = x4[i];
        float4 ww = w4[i];
        a.x = a.x * rs * ww.x;
        a.y = a.y * rs * ww.y;
        a.z = a.z * rs * ww.z;
        a.w = a.w * rs * ww.w;
        o4[i] = a;
    }
}

// ================= bf16x3 mma GEMM core (512 thr, warp tile 32x32) =========
__device__ __forceinline__ uint32_t packbf(__nv_bfloat16 a, __nv_bfloat16 b) {
    __nv_bfloat162 t;
    t.x = a; t.y = b;
    return *(uint32_t*)&t;
}

__device__ __forceinline__ void split4(float4 v, uint2& hi, uint2& lo) {
    __nv_bfloat16 hx = __float2bfloat16(v.x);
    __nv_bfloat16 hy = __float2bfloat16(v.y);
    __nv_bfloat16 hz = __float2bfloat16(v.z);
    __nv_bfloat16 hw = __float2bfloat16(v.w);
    __nv_bfloat16 lx = __float2bfloat16(v.x - __bfloat162float(hx));
    __nv_bfloat16 ly = __float2bfloat16(v.y - __bfloat162float(hy));
    __nv_bfloat16 lz = __float2bfloat16(v.z - __bfloat162float(hz));
    __nv_bfloat16 lw = __float2bfloat16(v.w - __bfloat162float(hw));
    hi.x = packbf(hx, hy); hi.y = packbf(hz, hw);
    lo.x = packbf(lx, ly); lo.y = packbf(lz, lw);
}

__device__ __forceinline__ void mma16(float* c, uint32_t a0, uint32_t a1,
                                      uint32_t a2, uint32_t a3,
                                      uint32_t b0, uint32_t b1) {
    asm volatile(
        "mma.sync.aligned.m16n8k16.row.col.f32.bf16.bf16.f32 "
        "{%0,%1,%2,%3}, {%4,%5,%6,%7}, {%8,%9}, {%0,%1,%2,%3};"
        : "+f"(c[0]), "+f"(c[1]), "+f"(c[2]), "+f"(c[3])
        : "r"(a0), "r"(a1), "r"(a2), "r"(a3), "r"(b0), "r"(b1));
}

__device__ __forceinline__ void ldsm4(uint32_t addr, uint32_t& r0, uint32_t& r1,
                                      uint32_t& r2, uint32_t& r3) {
    asm volatile(
        "ldmatrix.sync.aligned.m8n8.x4.shared.b16 {%0,%1,%2,%3}, [%4];"
        : "=r"(r0), "=r"(r1), "=r"(r2), "=r"(r3) : "r"(addr));
}

__device__ __forceinline__ uint32_t smem_u32(const void* p) {
    uint32_t a;
    asm("{ .reg .u64 t; cvta.to.shared.u64 t, %1; cvt.u32.u64 %0, t; }"
        : "=r"(a) : "l"(p));
    return a;
}

#define STRH 40
#define HBUF (128 * STRH)

__device__ __forceinline__ void gemm_core(
    const float* __restrict__ A, const float* __restrict__ B,
    const float* __restrict__ bias, const float* __restrict__ addsrc,
    float* __restrict__ C, int N, int K, int bm, int bn) {
    extern __shared__ __nv_bfloat16 sh[];
    __nv_bfloat16* Ah = sh;
    __nv_bfloat16* Al = sh + 2 * HBUF;
    __nv_bfloat16* Bh = sh + 4 * HBUF;
    __nv_bfloat16* Bl = sh + 6 * HBUF;
    const uint32_t shU = smem_u32(sh);

    const int tid = threadIdx.x;
    const int lane = tid & 31;
    const int warp = tid >> 5;
    const int wm = warp & 3;
    const int wn = warp >> 2;

    const uint32_t arow = (uint32_t)(lane & 15) * STRH + (uint32_t)(lane >> 4) * 8;
    const uint32_t brow = (uint32_t)(8 * (lane >> 4) + (lane & 7)) * STRH +
                          (uint32_t)((lane >> 3) & 1) * 8;

    float acc[2][4][4];
#pragma unroll
    for (int i = 0; i < 2; i++)
#pragma unroll
        for (int j = 0; j < 4; j++)
#pragma unroll
            for (int l = 0; l < 4; l++) acc[i][j][l] = 0.f;

    const int lrow = tid >> 2;
    const int lc4 = (tid & 3) * 8;
    const float* Ag = A + (size_t)(bm + lrow) * K + lc4;
    const float* Bg = B + (size_t)(bn + lrow) * K + lc4;

    float4 pa[2], pb[2];
#pragma unroll
    for (int p = 0; p < 2; p++) {
        pa[p] = *(const float4*)(Ag + p * 4);
        pb[p] = *(const float4*)(Bg + p * 4);
    }

    const int NKT = K / 32;

#pragma unroll
    for (int p = 0; p < 2; p++) {
        uint2 hi, lo;
        split4(pa[p], hi, lo);
        *(uint2*)(Ah + lrow * STRH + lc4 + p * 4) = hi;
        *(uint2*)(Al + lrow * STRH + lc4 + p * 4) = lo;
        split4(pb[p], hi, lo);
        *(uint2*)(Bh + lrow * STRH + lc4 + p * 4) = hi;
        *(uint2*)(Bl + lrow * STRH + lc4 + p * 4) = lo;
    }
    __syncthreads();

    for (int kt = 0; kt < NKT; kt++) {
        const int cur = kt & 1;
        const bool more = (kt + 1 < NKT);
        if (more) {
            size_t off = (size_t)(kt + 1) * 32;
#pragma unroll
            for (int p = 0; p < 2; p++) {
                pa[p] = *(const float4*)(Ag + off + p * 4);
                pb[p] = *(const float4*)(Bg + off + p * 4);
            }
        }
        const uint32_t AhU = shU + 2u * (cur * HBUF);
        const uint32_t AlU = shU + 2u * (2 * HBUF + cur * HBUF);
        const uint32_t BhU = shU + 2u * (4 * HBUF + cur * HBUF);
        const uint32_t BlU = shU + 2u * (6 * HBUF + cur * HBUF);

#pragma unroll
        for (int ks = 0; ks < 2; ks++) {
            const uint32_t k = ks * 16;
            uint32_t afh[2][4], afl[2][4], bfh[4][2], bfl[4][2];
#pragma unroll
            for (int mi = 0; mi < 2; mi++) {
                uint32_t ro = (uint32_t)(wm * 32 + mi * 16) * STRH + arow + k;
                ldsm4(AhU + 2u * ro, afh[mi][0], afh[mi][1], afh[mi][2],
                      afh[mi][3]);
                ldsm4(AlU + 2u * ro, afl[mi][0], afl[mi][1], afl[mi][2],
                      afl[mi][3]);
            }
#pragma unroll
            for (int p = 0; p < 2; p++) {
                uint32_t ro = (uint32_t)(wn * 32 + p * 16) * STRH + brow + k;
                ldsm4(BhU + 2u * ro, bfh[2 * p][0], bfh[2 * p][1],
                      bfh[2 * p + 1][0], bfh[2 * p + 1][1]);
                ldsm4(BlU + 2u * ro, bfl[2 * p][0], bfl[2 * p][1],
                      bfl[2 * p + 1][0], bfl[2 * p + 1][1]);
            }
#pragma unroll
            for (int mi = 0; mi < 2; mi++)
#pragma unroll
                for (int ni = 0; ni < 4; ni++)
                    mma16(acc[mi][ni], afh[mi][0], afh[mi][1], afh[mi][2],
                          afh[mi][3], bfh[ni][0], bfh[ni][1]);
#pragma unroll
            for (int mi = 0; mi < 2; mi++)
#pragma unroll
                for (int ni = 0; ni < 4; ni++)
                    mma16(acc[mi][ni], afh[mi][0], afh[mi][1], afh[mi][2],
                          afh[mi][3], bfl[ni][0], bfl[ni][1]);
#pragma unroll
            for (int mi = 0; mi < 2; mi++)
#pragma unroll
                for (int ni = 0; ni < 4; ni++)
                    mma16(acc[mi][ni], afl[mi][0], afl[mi][1], afl[mi][2],
                          afl[mi][3], bfh[ni][0], bfh[ni][1]);
        }

        if (more) {
            const int nxt = (kt + 1) & 1;
            __nv_bfloat16* Adh = Ah + nxt * HBUF;
            __nv_bfloat16* Adl = Al + nxt * HBUF;
            __nv_bfloat16* Bdh = Bh + nxt * HBUF;
            __nv_bfloat16* Bdl = Bl + nxt * HBUF;
#pragma unroll
            for (int p = 0; p < 2; p++) {
                uint2 hi, lo;
                split4(pa[p], hi, lo);
                *(uint2*)(Adh + lrow * STRH + lc4 + p * 4) = hi;
                *(uint2*)(Adl + lrow * STRH + lc4 + p * 4) = lo;
                split4(pb[p], hi, lo);
                *(uint2*)(Bdh + lrow * STRH + lc4 + p * 4) = hi;
                *(uint2*)(Bdl + lrow * STRH + lc4 + p * 4) = lo;
            }
        }
        __syncthreads();
    }

    const int g = lane >> 2;
    const int tg = lane & 3;
#pragma unroll
    for (int mi = 0; mi < 2; mi++) {
        int r0 = bm + wm * 32 + mi * 16 + g;
#pragma unroll
        for (int ni = 0; ni < 4; ni++) {
            int col = bn + wn * 32 + ni * 8 + tg * 2;
            float2 v0, v1;
            v0.x = acc[mi][ni][0]; v0.y = acc[mi][ni][1];
            v1.x = acc[mi][ni][2]; v1.y = acc[mi][ni][3];
            if (bias) {
                float2 bb = *(const float2*)(bias + col);
                v0.x += bb.x; v0.y += bb.y;
                v1.x += bb.x; v1.y += bb.y;
            }
            size_t i0 = (size_t)r0 * N + col;
            size_t i1 = (size_t)(r0 + 8) * N + col;
            if (addsrc) {
                float2 s0 = *(const float2*)(addsrc + i0);
                float2 s1 = *(const float2*)(addsrc + i1);
                v0.x += s0.x; v0.y += s0.y;
                v1.x += s1.x; v1.y += s1.y;
            }
            *(float2*)(C + i0) = v0;
            *(float2*)(C + i1) = v1;
        }
    }
}

// single GEMM (wo, down)
__global__ void __launch_bounds__(512) bf16gemm_nt(
    const float* __restrict__ A, const float* __restrict__ B,
    const float* __restrict__ bias, const float* __restrict__ addsrc,
    float* __restrict__ C, int M, int N, int K) {
    gemm_core(A, B, bias, addsrc, C, N, K, blockIdx.y * 128, blockIdx.x * 128);
}

// fused q/k/v (z selects weight+output); packs launch tails
__global__ void __launch_bounds__(512) qkv_gemm(
    const float* __restrict__ A, const float* __restrict__ wq,
    const float* __restrict__ wk, const float* __restrict__ wv,
    float* __restrict__ q, float* __restrict__ k, float* __restrict__ v) {
    const float* B = (blockIdx.z == 0) ? wq : (blockIdx.z == 1) ? wk : wv;
    float* C = (blockIdx.z == 0) ? q : (blockIdx.z == 1) ? k : v;
    gemm_core(A, B, nullptr, nullptr, C, HH, HH, blockIdx.y * 128,
              blockIdx.x * 128);
}

// fused mlogit/gate/up (z selects); packs launch tails
__global__ void __launch_bounds__(512) mlp3_gemm(
    const float* __restrict__ A, const float* __restrict__ mpw,
    const float* __restrict__ wg, const float* __restrict__ wu,
    const float* __restrict__ mpb, float* __restrict__ mlog,
    float* __restrict__ gate, float* __restrict__ up) {
    const float* B = (blockIdx.z == 0) ? mpw : (blockIdx.z == 1) ? wg : wu;
    const float* bias = (blockIdx.z == 0) ? mpb : nullptr;
    float* C = (blockIdx.z == 0) ? mlog : (blockIdx.z == 1) ? gate : up;
    gemm_core(A, B, bias, nullptr, C, II, HH, blockIdx.y * 128,
              blockIdx.x * 128);
}

// ---------------- RoPE (position_ids int32) ----------------
__global__ void rope_kernel(float* __restrict__ q, float* __restrict__ k,
                            const int* __restrict__ pos) {
    int idx = blockIdx.x * 256 + threadIdx.x;
    if (idx >= TT * NH * 64) return;
    int j = idx & 63;
    int th = idx >> 6;
    int t = th >> 5;
    float p = (float)pos[t];
    float ang = p * exp2f(-(float)j * (13.287712379549449f / 64.f));
    float s, c;
    sincosf(ang, &s, &c);
    size_t base = (size_t)th * HD + j;
    float q0 = q[base], q1 = q[base + 64];
    q[base] = q0 * c - q1 * s;
    q[base + 64] = q1 * c + q0 * s;
    float k0 = k[base], k1 = k[base + 64];
    k[base] = k0 * c - k1 * s;
    k[base + 64] = k1 * c + k0 * s;
}

// ---------------- attn predictor logits ----------------
__global__ void attn_pred_kernel(const float* __restrict__ hs,
                                 const float* __restrict__ w,
                                 const float* __restrict__ b,
                                 float* __restrict__ out) {
    int t = blockIdx.x;
    int warp = threadIdx.x >> 5, lane = threadIdx.x & 31;
    const float* hsrow = hs + (size_t)t * HH;
    for (int hh = 0; hh < 4; hh++) {
        int h = warp * 4 + hh;
        const float* wr = w + (size_t)h * HH;
        float s = 0.f;
        for (int kk = lane; kk < HH; kk += 32) s += hsrow[kk] * wr[kk];
        for (int o = 16; o > 0; o >>= 1) s += __shfl_xor_sync(0xffffffffu, s, o);
        if (lane == 0) out[t * NH + h] = s + b[h];
    }
}

// ---------------- head top-16 mask ----------------
__global__ void head_mask_kernel(const float* __restrict__ logit,
                                 float* __restrict__ mask) {
    int t = blockIdx.x;
    int h = threadIdx.x;
    float v = logit[t * NH + h];
    int rank = 0;
    for (int j = 0; j < NH; j++) {
        float vj = logit[t * NH + j];
        rank += (vj > v) || (vj == v && j < h);
    }
    mask[t * NH + h] = (rank < ATTN_TOPK) ? 1.f : 0.f;
}

// ---------------- attention: compacted active rows, NR in {2,4,8} ----------
template <int NR>
__device__ __forceinline__ void attn_body(
    const float* __restrict__ q, const float* __restrict__ k,
    const float* __restrict__ v, const int* __restrict__ amask,
    float* __restrict__ out, float* qs, float* P, float* red,
    int t0, int h, int tid, int nact, const int* ridx) {
    const float NEGF = -3.4e38f;
#pragma unroll
    for (int c = 0; c < NR; c++) {
        float val = 0.f;
        if (c < nact)
            val = q[(size_t)(t0 + ridx[c]) * HH + h * HD + tid] *
                  0.08838834764831845f;
        qs[c * HD + tid] = val;
    }
    __syncthreads();

    int jlim[NR];
#pragma unroll
    for (int c = 0; c < NR; c++) jlim[c] = (c < nact) ? (t0 + ridx[c]) : -1;
    const int nk = t0 + ridx[nact - 1] + 1;

    float lm[NR];
#pragma unroll
    for (int c = 0; c < NR; c++) lm[c] = NEGF;

    for (int j = tid; j < nk; j += 128) {
        float s[NR];
#pragma unroll
        for (int c = 0; c < NR; c++) s[c] = 0.f;
        bool am = (amask[j] != 0);
        if (am) {
            const float4* kr = (const float4*)(k + (size_t)j * HH + h * HD);
#pragma unroll
            for (int d4 = 0; d4 < 32; d4++) {
                float4 kv = kr[d4];
#pragma unroll
                for (int c = 0; c < NR; c++) {
                    float4 qv = *(const float4*)(qs + c * HD + d4 * 4);
                    s[c] += qv.x * kv.x + qv.y * kv.y + qv.z * kv.z +
                            qv.w * kv.w;
                }
            }
        }
#pragma unroll
        for (int c = 0; c < NR; c++) {
            float vv = (am && j <= jlim[c]) ? s[c] : NEGF;
            s[c] = vv;
            lm[c] = fmaxf(lm[c], vv);
        }
        float* pj = P + j * NR;
        if (NR == 8) {
            float4 o0, o1;
            o0.x = s[0]; o0.y = s[1]; o0.z = s[2]; o0.w = s[3];
            o1.x = s[NR > 4 ? 4 : 0]; o1.y = s[NR > 4 ? 5 : 0];
            o1.z = s[NR > 4 ? 6 : 0]; o1.w = s[NR > 4 ? 7 : 0];
            ((float4*)pj)[0] = o0;
            ((float4*)pj)[1] = o1;
        } else if (NR == 4) {
            float4 o0;
            o0.x = s[0]; o0.y = s[1];
            o0.z = s[NR > 2 ? 2 : 0]; o0.w = s[NR > 2 ? 3 : 0];
            ((float4*)pj)[0] = o0;
        } else {
            float2 o0;
            o0.x = s[0]; o0.y = s[1];
            ((float2*)pj)[0] = o0;
        }
    }
    float M[NR];
#pragma unroll
    for (int c = 0; c < NR; c++) {
        if (c >= nact) { M[c] = NEGF; continue; }
        red[tid] = lm[c];
        __syncthreads();
        for (int o = 64; o > 0; o >>= 1) {
            if (tid < o) red[tid] = fmaxf(red[tid], red[tid + o]);
            __syncthreads();
        }
        M[c] = red[0];
        __syncthreads();
    }
    float ls[NR];
#pragma unroll
    for (int c = 0; c < NR; c++) ls[c] = 0.f;
    for (int j = tid; j < nk; j += 128) {
        float* pj = P + j * NR;
        float e[NR];
#pragma unroll
        for (int c = 0; c < NR; c++) {
            float vv = (c < nact) ? __expf(pj[c] - M[c]) : 0.f;
            e[c] = vv;
            ls[c] += vv;
        }
#pragma unroll
        for (int c = 0; c < NR; c++) pj[c] = e[c];
    }
    float inv[NR];
#pragma unroll
    for (int c = 0; c < NR; c++) {
        if (c >= nact) { inv[c] = 0.f; continue; }
        red[tid] = ls[c];
        __syncthreads();
        for (int o = 64; o > 0; o >>= 1) {
            if (tid < o) red[tid] += red[tid + o];
            __syncthreads();
        }
        inv[c] = 1.f / red[0];
        __syncthreads();
    }
    float acc[NR];
#pragma unroll
    for (int c = 0; c < NR; c++) acc[c] = 0.f;
#pragma unroll 4
    for (int j = 0; j < nk; j++) {
        float vv = v[(size_t)j * HH + h * HD + tid];
        const float* pj = P + j * NR;
#pragma unroll
        for (int c = 0; c < NR; c++) acc[c] = fmaf(pj[c], vv, acc[c]);
    }
#pragma unroll
    for (int c = 0; c < NR; c++) {
        if (c >= nact) break;
        out[(size_t)(t0 + ridx[c]) * HH + h * HD + tid] = acc[c] * inv[c];
    }
}

__global__ void __launch_bounds__(128)
attention8_kernel(const float* __restrict__ q, const float* __restrict__ k,
                  const float* __restrict__ v, const float* __restrict__ hmask,
                  const int* __restrict__ amask, float* __restrict__ out) {
    extern __shared__ float asm_[];
    float* qs = asm_;
    float* P = asm_ + QB * HD;
    __shared__ float red[128];
    const int t0 = blockIdx.x * QB;
    const int h = blockIdx.y;
    const int tid = threadIdx.x;

    int ridx[QB];
    int nact = 0;
    float actv[QB];
#pragma unroll
    for (int r = 0; r < QB; r++) {
        actv[r] = hmask[(t0 + r) * NH + h];
        if (actv[r] != 0.f) ridx[nact++] = r;
    }
#pragma unroll
    for (int r = 0; r < QB; r++)
        if (actv[r] == 0.f)
            out[(size_t)(t0 + r) * HH + h * HD + tid] = 0.f;
    if (nact == 0) return;

    if (nact <= 2)
        attn_body<2>(q, k, v, amask, out, qs, P, red, t0, h, tid, nact, ridx);
    else if (nact <= 4)
        attn_body<4>(q, k, v, amask, out, qs, P, red, t0, h, tid, nact, ridx);
    else
        attn_body<8>(q, k, v, amask, out, qs, P, red, t0, h, tid, nact, ridx);
}

// ---------------- top-k radix select machinery ----------------
__device__ __forceinline__ unsigned fkey(float x) {
    unsigned b = __float_as_uint(x);
    return (b & 0x80000000u) ? ~b : (b | 0x80000000u);
}
__device__ __forceinline__ float unfkey(unsigned k) {
    unsigned b = (k & 0x80000000u) ? (k & 0x7fffffffu) : ~k;
    return __uint_as_float(b);
}

__global__ void mlp_thresh_kernel(const float* __restrict__ logits,
                                  float* __restrict__ thr) {
    int row = blockIdx.x;
    const float* lr = logits + (size_t)row * II;
    __shared__ unsigned hist[256];
    __shared__ unsigned sh_sel, sh_kk;
    int tid = threadIdx.x;
    unsigned prefix = 0;
    unsigned kk = MLP_TOPK;
    for (int shift = 24; shift >= 0; shift -= 8) {
        hist[tid] = 0;
        __syncthreads();
        for (int i = tid; i < II; i += 256) {
            unsigned u = fkey(lr[i]);
            bool ok = (shift == 24) || ((u >> (shift + 8)) == prefix);
            if (ok) atomicAdd(&hist[(u >> shift) & 255u], 1u);
        }
        __syncthreads();
        if (tid == 0) {
            unsigned c = 0;
            int sel = 0;
            for (int b = 255; b >= 0; b--) {
                c += hist[b];
                if (c >= kk) { sel = b; break; }
            }
            sh_sel = (unsigned)sel;
            sh_kk = kk - (c - hist[sel]);
        }
        __syncthreads();
        prefix = (prefix << 8) | sh_sel;
        kk = sh_kk;
        __syncthreads();
    }
    if (tid == 0) thr[row] = unfkey(prefix);
}

#define BAND 4e-3f
__global__ void mlp_correct_kernel(float* __restrict__ mlog,
                                   const float* __restrict__ hs,
                                   const float* __restrict__ w,
                                   const float* __restrict__ b,
                                   const float* __restrict__ thr) {
    int row = blockIdx.x;
    int tid = threadIdx.x;
    __shared__ int cnt;
    __shared__ int idxs[1024];
    if (tid == 0) cnt = 0;
    __syncthreads();
    float th = thr[row];
    float* lr = mlog + (size_t)row * II;
    for (int i = tid; i < II; i += 256) {
        if (fabsf(lr[i] - th) <= BAND) {
            int p = atomicAdd(&cnt, 1);
            if (p < 1024) idxs[p] = i;
        }
    }
    __syncthreads();
    int n = cnt < 1024 ? cnt : 1024;
    int warp = tid >> 5, lane = tid & 31;
    const float* hsr = hs + (size_t)row * HH;
    for (int c = warp; c < n; c += 8) {
        int i = idxs[c];
        const float* wr = w + (size_t)i * HH;
        float s = 0.f;
        for (int kk = lane; kk < HH; kk += 32) s += hsr[kk] * wr[kk];
        for (int o = 16; o > 0; o >>= 1) s += __shfl_xor_sync(0xffffffffu, s, o);
        if (lane == 0) lr[i] = s + b[i];
    }
}

__global__ void mlp_topk_kernel(const float* __restrict__ logits,
                                float* __restrict__ mask) {
    int row = blockIdx.x;
    const float* lr = logits + (size_t)row * II;
    __shared__ unsigned hist[256];
    __shared__ unsigned sh_sel, sh_kk;
    __shared__ unsigned sh_cnt[2];
    int tid = threadIdx.x;
    unsigned prefix = 0;
    unsigned kk = MLP_TOPK;
    for (int shift = 24; shift >= 0; shift -= 8) {
        hist[tid] = 0;
        __syncthreads();
        for (int i = tid; i < II; i += 256) {
            unsigned u = fkey(lr[i]);
            bool ok = (shift == 24) || ((u >> (shift + 8)) == prefix);
            if (ok) atomicAdd(&hist[(u >> shift) & 255u], 1u);
        }
        __syncthreads();
        if (tid == 0) {
            unsigned c = 0;
            int sel = 0;
            for (int b = 255; b >= 0; b--) {
                c += hist[b];
                if (c >= kk) { sel = b; break; }
            }
            sh_sel = (unsigned)sel;
            sh_kk = kk - (c - hist[sel]);
        }
        __syncthreads();
        prefix = (prefix << 8) | sh_sel;
        kk = sh_kk;
        __syncthreads();
    }
    unsigned thresh = prefix;
    if (tid < 2) sh_cnt[tid] = 0;
    __syncthreads();
    unsigned lg = 0, le = 0;
    for (int i = tid; i < II; i += 256) {
        unsigned u = fkey(lr[i]);
        if (u > thresh) lg++;
        else if (u == thresh) le++;
    }
    atomicAdd(&sh_cnt[0], lg);
    atomicAdd(&sh_cnt[1], le);
    __syncthreads();
    unsigned g = sh_cnt[0], e = sh_cnt[1];
    float* mr = mask + (size_t)row * II;
    if (g + e == MLP_TOPK) {
        for (int i = tid; i < II; i += 256)
            mr[i] = (fkey(lr[i]) >= thresh) ? 1.f : 0.f;
    } else {
        for (int i = tid; i < II; i += 256)
            mr[i] = (fkey(lr[i]) > thresh) ? 1.f : 0.f;
        __syncthreads();
        if (tid == 0) {
            unsigned quota = MLP_TOPK - g;
            for (int i = 0; i < II && quota > 0; i++) {
                if (fkey(lr[i]) == thresh) { mr[i] = 1.f; quota--; }
            }
        }
    }
}

// ---------------- silu * up * mask ----------------
__global__ void silu_mul_mask_kernel(float* __restrict__ gate,
                                     const float* __restrict__ up,
                                     const float* __restrict__ mask, int n) {
    int i = blockIdx.x * 256 + threadIdx.x;
    if (i < n) {
        float x = gate[i];
        float si = x / (1.f + __expf(-x));
        gate[i] = si * up[i] * mask[i];
    }
}

// ---------------- launch ----------------
extern "C" void kernel_launch(void* const* d_in, const int* in_sizes, int n_in,
                              void* d_out, int out_size) {
    const float* hidden = (const float*)d_in[0];
    const int* amask = (const int*)d_in[1];
    const int* pos = (const int*)d_in[2];
    const float* wq = (const float*)d_in[3];
    const float* wk = (const float*)d_in[4];
    const float* wv = (const float*)d_in[5];
    const float* wo = (const float*)d_in[6];
    const float* w_gate = (const float*)d_in[7];
    const float* w_up = (const float*)d_in[8];
    const float* w_down = (const float*)d_in[9];
    const float* ln1 = (const float*)d_in[10];
    const float* ln2 = (const float*)d_in[11];
    const float* apw = (const float*)d_in[12];
    const float* apb = (const float*)d_in[13];
    const float* mpw = (const float*)d_in[14];
    const float* mpb = (const float*)d_in[15];
    float* out = (float*)d_out;

    float *hs, *q, *k, *v, *attn, *res2, *hlog, *hmask, *mlog, *fcm, *gate, *up,
        *thr;
    cudaGetSymbolAddress((void**)&hs, g_hs);
    cudaGetSymbolAddress((void**)&q, g_q);
    cudaGetSymbolAddress((void**)&k, g_k);
    cudaGetSymbolAddress((void**)&v, g_v);
    cudaGetSymbolAddress((void**)&attn, g_attn);
    cudaGetSymbolAddress((void**)&res2, g_res2);
    cudaGetSymbolAddress((void**)&hlog, g_hlogit);
    cudaGetSymbolAddress((void**)&hmask, g_headmask);
    cudaGetSymbolAddress((void**)&mlog, g_mlogit);
    cudaGetSymbolAddress((void**)&fcm, g_fcmask);
    cudaGetSymbolAddress((void**)&gate, g_gate);
    cudaGetSymbolAddress((void**)&up, g_up);
    cudaGetSymbolAddress((void**)&thr, g_thr);

    const int SMEM_B = 8 * HBUF * (int)sizeof(__nv_bfloat16);   // 81920 B
    cudaFuncSetAttribute(bf16gemm_nt,
                         cudaFuncAttributeMaxDynamicSharedMemorySize, SMEM_B);
    cudaFuncSetAttribute(qkv_gemm,
                         cudaFuncAttributeMaxDynamicSharedMemorySize, SMEM_B);
    cudaFuncSetAttribute(mlp3_gemm,
                         cudaFuncAttributeMaxDynamicSharedMemorySize, SMEM_B);
    const int SMEM_A = (QB * HD + TT * QB) * (int)sizeof(float);  // 69632 B
    cudaFuncSetAttribute(attention8_kernel,
                         cudaFuncAttributeMaxDynamicSharedMemorySize, SMEM_A);

    rmsnorm_kernel<<<TT, 256>>>(hidden, ln1, hs);
    // fused q,k,v: one launch, 1536 blocks -> packed waves
    qkv_gemm<<<dim3(HH / 128, TT / 128, 3), 512, SMEM_B>>>(hs, wq, wk, wv, q, k,
                                                           v);
    rope_kernel<<<(TT * NH * 64 + 255) / 256, 256>>>(q, k, pos);
    attn_pred_kernel<<<TT, 256>>>(hs, apw, apb, hlog);
    head_mask_kernel<<<TT, 32>>>(hlog, hmask);
    attention8_kernel<<<dim3(TT / QB, NH), 128, SMEM_A>>>(q, k, v, hmask, amask,
                                                          attn);
    bf16gemm_nt<<<dim3(HH / 128, TT / 128), 512, SMEM_B>>>(attn, wo, nullptr,
                                                           hidden, res2, TT, HH,
                                                           HH);
    rmsnorm_kernel<<<TT, 256>>>(res2, ln2, hs);
    // fused mlogit,gate,up: one launch, 4128 blocks
    mlp3_gemm<<<dim3(II / 128, TT / 128, 3), 512, SMEM_B>>>(hs, mpw, w_gate,
                                                            w_up, mpb, mlog,
                                                            gate, up);
    mlp_thresh_kernel<<<TT, 256>>>(mlog, thr);
    mlp_correct_kernel<<<TT, 256>>>(mlog, hs, mpw, mpb, thr);
    mlp_topk_kernel<<<TT, 256>>>(mlog, fcm);
    silu_mul_mask_kernel<<<(TT * II + 255) / 256, 256>>>(gate, up, fcm, TT * II);
    bf16gemm_nt<<<dim3(HH / 128, TT / 128), 512, SMEM_B>>>(gate, w_down,
                                                           nullptr, res2, out,
                                                           TT, HH, II);
}

// round 17
// speedup vs baseline: 1.1467x; 1.0165x over previous
#include <cuda_runtime.h>
#include <cuda_bf16.h>
#include <math.h>
#include <stdint.h>

#define TT 2048
#define HH 4096
#define NH 32
#define HD 128
#define II 11008
#define ATTN_TOPK 16
#define MLP_TOPK 2048
#define QB 8

// ---------------- scratch (fp32) ----------------
__device__ float g_hs[TT * HH];
__device__ float g_q[TT * HH];
__device__ float g_k[TT * HH];
__device__ float g_v[TT * HH];
__device__ float g_res2[TT * HH];
__device__ float g_hlogit[TT * NH];
__device__ float g_headmask[TT * NH];
__device__ float g_mlogit[TT * II];
__device__ float g_fcmask[TT * II];
__device__ float g_gate[TT * II];
__device__ float g_up[TT * II];
__device__ float g_thr[TT];

// ---------------- scratch (bf16 hi/lo splits) ----------------
__device__ __nv_bfloat16 g_hs_h[TT * HH], g_hs_l[TT * HH];
__device__ __nv_bfloat16 g_attn_h[TT * HH], g_attn_l[TT * HH];
__device__ __nv_bfloat16 g_int_h[TT * II], g_int_l[TT * II];
__device__ __nv_bfloat16 g_wq_h[HH * HH], g_wq_l[HH * HH];
__device__ __nv_bfloat16 g_wk_h[HH * HH], g_wk_l[HH * HH];
__device__ __nv_bfloat16 g_wv_h[HH * HH], g_wv_l[HH * HH];
__device__ __nv_bfloat16 g_wo_h[HH * HH], g_wo_l[HH * HH];
__device__ __nv_bfloat16 g_mpw_h[(size_t)II * HH], g_mpw_l[(size_t)II * HH];
__device__ __nv_bfloat16 g_wg_h[(size_t)II * HH], g_wg_l[(size_t)II * HH];
__device__ __nv_bfloat16 g_wu_h[(size_t)II * HH], g_wu_l[(size_t)II * HH];
__device__ __nv_bfloat16 g_wd_h[(size_t)II * HH], g_wd_l[(size_t)II * HH];

// ---------------- split helpers ----------------
__device__ __forceinline__ uint32_t packbf(__nv_bfloat16 a, __nv_bfloat16 b) {
    __nv_bfloat162 t;
    t.x = a; t.y = b;
    return *(uint32_t*)&t;
}

__device__ __forceinline__ void split4(float4 v, uint2& hi, uint2& lo) {
    __nv_bfloat16 hx = __float2bfloat16(v.x);
    __nv_bfloat16 hy = __float2bfloat16(v.y);
    __nv_bfloat16 hz = __float2bfloat16(v.z);
    __nv_bfloat16 hw = __float2bfloat16(v.w);
    __nv_bfloat16 lx = __float2bfloat16(v.x - __bfloat162float(hx));
    __nv_bfloat16 ly = __float2bfloat16(v.y - __bfloat162float(hy));
    __nv_bfloat16 lz = __float2bfloat16(v.z - __bfloat162float(hz));
    __nv_bfloat16 lw = __float2bfloat16(v.w - __bfloat162float(hw));
    hi.x = packbf(hx, hy); hi.y = packbf(hz, hw);
    lo.x = packbf(lx, ly); lo.y = packbf(lz, lw);
}

// elementwise fp32 -> bf16 hi/lo
__global__ void split_kernel(const float* __restrict__ x,
                             __nv_bfloat16* __restrict__ xh,
                             __nv_bfloat16* __restrict__ xl, int n4) {
    int i = blockIdx.x * 256 + threadIdx.x;
    if (i < n4) {
        float4 v = ((const float4*)x)[i];
        uint2 h, l;
        split4(v, h, l);
        ((uint2*)xh)[i] = h;
        ((uint2*)xl)[i] = l;
    }
}

// ---------------- RMSNorm (emits float + bf16 hi/lo) ----------------
__global__ void rmsnorm_kernel(const float* __restrict__ x,
                               const float* __restrict__ w,
                               float* __restrict__ out,
                               __nv_bfloat16* __restrict__ outh,
                               __nv_bfloat16* __restrict__ outl) {
    int row = blockIdx.x;
    const float4* x4 = (const float4*)(x + (size_t)row * HH);
    const float4* w4 = (const float4*)w;
    float s = 0.f;
    for (int i = threadIdx.x; i < HH / 4; i += 256) {
        float4 v = x4[i];
        s += v.x * v.x + v.y * v.y + v.z * v.z + v.w * v.w;
    }
    __shared__ float red[256];
    red[threadIdx.x] = s;
    __syncthreads();
    for (int o = 128; o > 0; o >>= 1) {
        if (threadIdx.x < o) red[threadIdx.x] += red[threadIdx.x + o];
        __syncthreads();
    }
    float rs = rsqrtf(red[0] / (float)HH + 1e-6f);
    float4* o4 = (float4*)(out + (size_t)row * HH);
    uint2* oh = (uint2*)(outh + (size_t)row * HH);
    uint2* ol = (uint2*)(outl + (size_t)row * HH);
    for (int i = threadIdx.x; i < HH / 4; i += 256) {
        float4 a = x4[i];
        float4 ww = w4[i];
        a.x = a.x * rs * ww.x;
        a.y = a.y * rs * ww.y;
        a.z = a.z * rs * ww.z;
        a.w = a.w * rs * ww.w;
        o4[i] = a;
        uint2 h, l;
        split4(a, h, l);
        oh[i] = h;
        ol[i] = l;
    }
}

// ================= bf16x3 mma GEMM core (pre-split operands) ===============
__device__ __forceinline__ void mma16(float* c, uint32_t a0, uint32_t a1,
                                      uint32_t a2, uint32_t a3,
                                      uint32_t b0, uint32_t b1) {
    asm volatile(
        "mma.sync.aligned.m16n8k16.row.col.f32.bf16.bf16.f32 "
        "{%0,%1,%2,%3}, {%4,%5,%6,%7}, {%8,%9}, {%0,%1,%2,%3};"
        : "+f"(c[0]), "+f"(c[1]), "+f"(c[2]), "+f"(c[3])
        : "r"(a0), "r"(a1), "r"(a2), "r"(a3), "r"(b0), "r"(b1));
}

__device__ __forceinline__ void ldsm4(uint32_t addr, uint32_t& r0, uint32_t& r1,
                                      uint32_t& r2, uint32_t& r3) {
    asm volatile(
        "ldmatrix.sync.aligned.m8n8.x4.shared.b16 {%0,%1,%2,%3}, [%4];"
        : "=r"(r0), "=r"(r1), "=r"(r2), "=r"(r3) : "r"(addr));
}

__device__ __forceinline__ uint32_t smem_u32(const void* p) {
    uint32_t a;
    asm("{ .reg .u64 t; cvta.to.shared.u64 t, %1; cvt.u32.u64 %0, t; }"
        : "=r"(a) : "l"(p));
    return a;
}

#define STRH 40
#define HBUF (128 * STRH)

__device__ __forceinline__ void gemm_core(
    const __nv_bfloat16* __restrict__ Ah_g,
    const __nv_bfloat16* __restrict__ Al_g,
    const __nv_bfloat16* __restrict__ Bh_g,
    const __nv_bfloat16* __restrict__ Bl_g,
    const float* __restrict__ bias, const float* __restrict__ addsrc,
    float* __restrict__ C, int N, int K, int bm, int bn) {
    extern __shared__ __nv_bfloat16 sh[];
    __nv_bfloat16* Ah = sh;
    __nv_bfloat16* Al = sh + 2 * HBUF;
    __nv_bfloat16* Bh = sh + 4 * HBUF;
    __nv_bfloat16* Bl = sh + 6 * HBUF;
    const uint32_t shU = smem_u32(sh);

    const int tid = threadIdx.x;
    const int lane = tid & 31;
    const int warp = tid >> 5;
    const int wm = warp & 3;
    const int wn = warp >> 2;

    const uint32_t arow = (uint32_t)(lane & 15) * STRH + (uint32_t)(lane >> 4) * 8;
    const uint32_t brow = (uint32_t)(8 * (lane >> 4) + (lane & 7)) * STRH +
                          (uint32_t)((lane >> 3) & 1) * 8;

    float acc[2][4][4];
#pragma unroll
    for (int i = 0; i < 2; i++)
#pragma unroll
        for (int j = 0; j < 4; j++)
#pragma unroll
            for (int l = 0; l < 4; l++) acc[i][j][l] = 0.f;

    const int lrow = tid >> 2;        // 0..127
    const int lc8 = (tid & 3) * 8;    // halves
    const __nv_bfloat16* Agh = Ah_g + (size_t)(bm + lrow) * K + lc8;
    const __nv_bfloat16* Agl = Al_g + (size_t)(bm + lrow) * K + lc8;
    const __nv_bfloat16* Bgh = Bh_g + (size_t)(bn + lrow) * K + lc8;
    const __nv_bfloat16* Bgl = Bl_g + (size_t)(bn + lrow) * K + lc8;

    uint4 pah, pal, pbh, pbl;
    pah = *(const uint4*)(Agh);
    pal = *(const uint4*)(Agl);
    pbh = *(const uint4*)(Bgh);
    pbl = *(const uint4*)(Bgl);

    const int NKT = K / 32;
    const uint32_t so = lrow * STRH + lc8;

    *(uint4*)(Ah + so) = pah;
    *(uint4*)(Al + so) = pal;
    *(uint4*)(Bh + so) = pbh;
    *(uint4*)(Bl + so) = pbl;
    __syncthreads();

    for (int kt = 0; kt < NKT; kt++) {
        const int cur = kt & 1;
        const bool more = (kt + 1 < NKT);
        if (more) {
            size_t off = (size_t)(kt + 1) * 32;
            pah = *(const uint4*)(Agh + off);
            pal = *(const uint4*)(Agl + off);
            pbh = *(const uint4*)(Bgh + off);
            pbl = *(const uint4*)(Bgl + off);
        }
        const uint32_t AhU = shU + 2u * (cur * HBUF);
        const uint32_t AlU = shU + 2u * (2 * HBUF + cur * HBUF);
        const uint32_t BhU = shU + 2u * (4 * HBUF + cur * HBUF);
        const uint32_t BlU = shU + 2u * (6 * HBUF + cur * HBUF);

#pragma unroll
        for (int ks = 0; ks < 2; ks++) {
            const uint32_t k = ks * 16;
            uint32_t afh[2][4], afl[2][4], bfh[4][2], bfl[4][2];
#pragma unroll
            for (int mi = 0; mi < 2; mi++) {
                uint32_t ro = (uint32_t)(wm * 32 + mi * 16) * STRH + arow + k;
                ldsm4(AhU + 2u * ro, afh[mi][0], afh[mi][1], afh[mi][2],
                      afh[mi][3]);
                ldsm4(AlU + 2u * ro, afl[mi][0], afl[mi][1], afl[mi][2],
                      afl[mi][3]);
            }
#pragma unroll
            for (int p = 0; p < 2; p++) {
                uint32_t ro = (uint32_t)(wn * 32 + p * 16) * STRH + brow + k;
                ldsm4(BhU + 2u * ro, bfh[2 * p][0], bfh[2 * p][1],
                      bfh[2 * p + 1][0], bfh[2 * p + 1][1]);
                ldsm4(BlU + 2u * ro, bfl[2 * p][0], bfl[2 * p][1],
                      bfl[2 * p + 1][0], bfl[2 * p + 1][1]);
            }
#pragma unroll
            for (int mi = 0; mi < 2; mi++)
#pragma unroll
                for (int ni = 0; ni < 4; ni++)
                    mma16(acc[mi][ni], afh[mi][0], afh[mi][1], afh[mi][2],
                          afh[mi][3], bfh[ni][0], bfh[ni][1]);
#pragma unroll
            for (int mi = 0; mi < 2; mi++)
#pragma unroll
                for (int ni = 0; ni < 4; ni++)
                    mma16(acc[mi][ni], afh[mi][0], afh[mi][1], afh[mi][2],
                          afh[mi][3], bfl[ni][0], bfl[ni][1]);
#pragma unroll
            for (int mi = 0; mi < 2; mi++)
#pragma unroll
                for (int ni = 0; ni < 4; ni++)
                    mma16(acc[mi][ni], afl[mi][0], afl[mi][1], afl[mi][2],
                          afl[mi][3], bfh[ni][0], bfh[ni][1]);
        }

        if (more) {
            const int nxt = (kt + 1) & 1;
            *(uint4*)(Ah + nxt * HBUF + so) = pah;
            *(uint4*)(Al + nxt * HBUF + so) = pal;
            *(uint4*)(Bh + nxt * HBUF + so) = pbh;
            *(uint4*)(Bl + nxt * HBUF + so) = pbl;
        }
        __syncthreads();
    }

    const int g = lane >> 2;
    const int tg = lane & 3;
#pragma unroll
    for (int mi = 0; mi < 2; mi++) {
        int r0 = bm + wm * 32 + mi * 16 + g;
#pragma unroll
        for (int ni = 0; ni < 4; ni++) {
            int col = bn + wn * 32 + ni * 8 + tg * 2;
            float2 v0, v1;
            v0.x = acc[mi][ni][0]; v0.y = acc[mi][ni][1];
            v1.x = acc[mi][ni][2]; v1.y = acc[mi][ni][3];
            if (bias) {
                float2 bb = *(const float2*)(bias + col);
                v0.x += bb.x; v0.y += bb.y;
                v1.x += bb.x; v1.y += bb.y;
            }
            size_t i0 = (size_t)r0 * N + col;
            size_t i1 = (size_t)(r0 + 8) * N + col;
            if (addsrc) {
                float2 s0 = *(const float2*)(addsrc + i0);
                float2 s1 = *(const float2*)(addsrc + i1);
                v0.x += s0.x; v0.y += s0.y;
                v1.x += s1.x; v1.y += s1.y;
            }
            *(float2*)(C + i0) = v0;
            *(float2*)(C + i1) = v1;
        }
    }
}

// single GEMM (wo, down)
__global__ void __launch_bounds__(512) bf16gemm_nt(
    const __nv_bfloat16* __restrict__ Ah, const __nv_bfloat16* __restrict__ Al,
    const __nv_bfloat16* __restrict__ Bh, const __nv_bfloat16* __restrict__ Bl,
    const float* __restrict__ bias, const float* __restrict__ addsrc,
    float* __restrict__ C, int N, int K) {
    gemm_core(Ah, Al, Bh, Bl, bias, addsrc, C, N, K, blockIdx.y * 128,
              blockIdx.x * 128);
}

// fused q/k/v
__global__ void __launch_bounds__(512) qkv_gemm(
    const __nv_bfloat16* __restrict__ Ah, const __nv_bfloat16* __restrict__ Al,
    float* __restrict__ q, float* __restrict__ k, float* __restrict__ v) {
    const __nv_bfloat16* Bh =
        (blockIdx.z == 0) ? g_wq_h : (blockIdx.z == 1) ? g_wk_h : g_wv_h;
    const __nv_bfloat16* Bl =
        (blockIdx.z == 0) ? g_wq_l : (blockIdx.z == 1) ? g_wk_l : g_wv_l;
    float* C = (blockIdx.z == 0) ? q : (blockIdx.z == 1) ? k : v;
    gemm_core(Ah, Al, Bh, Bl, nullptr, nullptr, C, HH, HH, blockIdx.y * 128,
              blockIdx.x * 128);
}

// fused mlogit/gate/up
__global__ void __launch_bounds__(512) mlp3_gemm(
    const __nv_bfloat16* __restrict__ Ah, const __nv_bfloat16* __restrict__ Al,
    const float* __restrict__ mpb, float* __restrict__ mlog,
    float* __restrict__ gate, float* __restrict__ up) {
    const __nv_bfloat16* Bh =
        (blockIdx.z == 0) ? g_mpw_h : (blockIdx.z == 1) ? g_wg_h : g_wu_h;
    const __nv_bfloat16* Bl =
        (blockIdx.z == 0) ? g_mpw_l : (blockIdx.z == 1) ? g_wg_l : g_wu_l;
    const float* bias = (blockIdx.z == 0) ? mpb : nullptr;
    float* C = (blockIdx.z == 0) ? mlog : (blockIdx.z == 1) ? gate : up;
    gemm_core(Ah, Al, Bh, Bl, bias, nullptr, C, II, HH, blockIdx.y * 128,
              blockIdx.x * 128);
}

// ---------------- RoPE (position_ids int32) ----------------
__global__ void rope_kernel(float* __restrict__ q, float* __restrict__ k,
                            const int* __restrict__ pos) {
    int idx = blockIdx.x * 256 + threadIdx.x;
    if (idx >= TT * NH * 64) return;
    int j = idx & 63;
    int th = idx >> 6;
    int t = th >> 5;
    float p = (float)pos[t];
    float ang = p * exp2f(-(float)j * (13.287712379549449f / 64.f));
    float s, c;
    sincosf(ang, &s, &c);
    size_t base = (size_t)th * HD + j;
    float q0 = q[base], q1 = q[base + 64];
    q[base] = q0 * c - q1 * s;
    q[base + 64] = q1 * c + q0 * s;
    float k0 = k[base], k1 = k[base + 64];
    k[base] = k0 * c - k1 * s;
    k[base + 64] = k1 * c + k0 * s;
}

// ---------------- attn predictor logits ----------------
__global__ void attn_pred_kernel(const float* __restrict__ hs,
                                 const float* __restrict__ w,
                                 const float* __restrict__ b,
                                 float* __restrict__ out) {
    int t = blockIdx.x;
    int warp = threadIdx.x >> 5, lane = threadIdx.x & 31;
    const float* hsrow = hs + (size_t)t * HH;
    for (int hh = 0; hh < 4; hh++) {
        int h = warp * 4 + hh;
        const float* wr = w + (size_t)h * HH;
        float s = 0.f;
        for (int kk = lane; kk < HH; kk += 32) s += hsrow[kk] * wr[kk];
        for (int o = 16; o > 0; o >>= 1) s += __shfl_xor_sync(0xffffffffu, s, o);
        if (lane == 0) out[t * NH + h] = s + b[h];
    }
}

// ---------------- head top-16 mask ----------------
__global__ void head_mask_kernel(const float* __restrict__ logit,
                                 float* __restrict__ mask) {
    int t = blockIdx.x;
    int h = threadIdx.x;
    float v = logit[t * NH + h];
    int rank = 0;
    for (int j = 0; j < NH; j++) {
        float vj = logit[t * NH + j];
        rank += (vj > v) || (vj == v && j < h);
    }
    mask[t * NH + h] = (rank < ATTN_TOPK) ? 1.f : 0.f;
}

// ---------------- attention (emits bf16 hi/lo), compacted rows ----------
__device__ __forceinline__ void store_hl(__nv_bfloat16* oh, __nv_bfloat16* ol,
                                         size_t idx, float val) {
    __nv_bfloat16 h = __float2bfloat16(val);
    oh[idx] = h;
    ol[idx] = __float2bfloat16(val - __bfloat162float(h));
}

template <int NR>
__device__ __forceinline__ void attn_body(
    const float* __restrict__ q, const float* __restrict__ k,
    const float* __restrict__ v, const int* __restrict__ amask,
    __nv_bfloat16* __restrict__ oh, __nv_bfloat16* __restrict__ ol,
    float* qs, float* P, float* red, int t0, int h, int tid, int nact,
    const int* ridx) {
    const float NEGF = -3.4e38f;
#pragma unroll
    for (int c = 0; c < NR; c++) {
        float val = 0.f;
        if (c < nact)
            val = q[(size_t)(t0 + ridx[c]) * HH + h * HD + tid] *
                  0.08838834764831845f;
        qs[c * HD + tid] = val;
    }
    __syncthreads();

    int jlim[NR];
#pragma unroll
    for (int c = 0; c < NR; c++) jlim[c] = (c < nact) ? (t0 + ridx[c]) : -1;
    const int nk = t0 + ridx[nact - 1] + 1;

    float lm[NR];
#pragma unroll
    for (int c = 0; c < NR; c++) lm[c] = NEGF;

    for (int j = tid; j < nk; j += 128) {
        float s[NR];
#pragma unroll
        for (int c = 0; c < NR; c++) s[c] = 0.f;
        bool am = (amask[j] != 0);
        if (am) {
            const float4* kr = (const float4*)(k + (size_t)j * HH + h * HD);
#pragma unroll
            for (int d4 = 0; d4 < 32; d4++) {
                float4 kv = kr[d4];
#pragma unroll
                for (int c = 0; c < NR; c++) {
                    float4 qv = *(const float4*)(qs + c * HD + d4 * 4);
                    s[c] += qv.x * kv.x + qv.y * kv.y + qv.z * kv.z +
                            qv.w * kv.w;
                }
            }
        }
#pragma unroll
        for (int c = 0; c < NR; c++) {
            float vv = (am && j <= jlim[c]) ? s[c] : NEGF;
            s[c] = vv;
            lm[c] = fmaxf(lm[c], vv);
        }
        float* pj = P + j * NR;
        if (NR == 8) {
            float4 o0, o1;
            o0.x = s[0]; o0.y = s[1]; o0.z = s[2]; o0.w = s[3];
            o1.x = s[NR > 4 ? 4 : 0]; o1.y = s[NR > 4 ? 5 : 0];
            o1.z = s[NR > 4 ? 6 : 0]; o1.w = s[NR > 4 ? 7 : 0];
            ((float4*)pj)[0] = o0;
            ((float4*)pj)[1] = o1;
        } else if (NR == 4) {
            float4 o0;
            o0.x = s[0]; o0.y = s[1];
            o0.z = s[NR > 2 ? 2 : 0]; o0.w = s[NR > 2 ? 3 : 0];
            ((float4*)pj)[0] = o0;
        } else {
            float2 o0;
            o0.x = s[0]; o0.y = s[1];
            ((float2*)pj)[0] = o0;
        }
    }
    float M[NR];
#pragma unroll
    for (int c = 0; c < NR; c++) {
        if (c >= nact) { M[c] = NEGF; continue; }
        red[tid] = lm[c];
        __syncthreads();
        for (int o = 64; o > 0; o >>= 1) {
            if (tid < o) red[tid] = fmaxf(red[tid], red[tid + o]);
            __syncthreads();
        }
        M[c] = red[0];
        __syncthreads();
    }
    float ls[NR];
#pragma unroll
    for (int c = 0; c < NR; c++) ls[c] = 0.f;
    for (int j = tid; j < nk; j += 128) {
        float* pj = P + j * NR;
        float e[NR];
#pragma unroll
        for (int c = 0; c < NR; c++) {
            float vv = (c < nact) ? __expf(pj[c] - M[c]) : 0.f;
            e[c] = vv;
            ls[c] += vv;
        }
#pragma unroll
        for (int c = 0; c < NR; c++) pj[c] = e[c];
    }
    float inv[NR];
#pragma unroll
    for (int c = 0; c < NR; c++) {
        if (c >= nact) { inv[c] = 0.f; continue; }
        red[tid] = ls[c];
        __syncthreads();
        for (int o = 64; o > 0; o >>= 1) {
            if (tid < o) red[tid] += red[tid + o];
            __syncthreads();
        }
        inv[c] = 1.f / red[0];
        __syncthreads();
    }
    float acc[NR];
#pragma unroll
    for (int c = 0; c < NR; c++) acc[c] = 0.f;
#pragma unroll 4
    for (int j = 0; j < nk; j++) {
        float vv = v[(size_t)j * HH + h * HD + tid];
        const float* pj = P + j * NR;
#pragma unroll
        for (int c = 0; c < NR; c++) acc[c] = fmaf(pj[c], vv, acc[c]);
    }
#pragma unroll
    for (int c = 0; c < NR; c++) {
        if (c >= nact) break;
        store_hl(oh, ol, (size_t)(t0 + ridx[c]) * HH + h * HD + tid,
                 acc[c] * inv[c]);
    }
}

__global__ void __launch_bounds__(128)
attention8_kernel(const float* __restrict__ q, const float* __restrict__ k,
                  const float* __restrict__ v, const float* __restrict__ hmask,
                  const int* __restrict__ amask,
                  __nv_bfloat16* __restrict__ oh,
                  __nv_bfloat16* __restrict__ ol) {
    extern __shared__ float asm_[];
    float* qs = asm_;
    float* P = asm_ + QB * HD;
    __shared__ float red[128];
    const int t0 = blockIdx.x * QB;
    const int h = blockIdx.y;
    const int tid = threadIdx.x;

    int ridx[QB];
    int nact = 0;
    float actv[QB];
#pragma unroll
    for (int r = 0; r < QB; r++) {
        actv[r] = hmask[(t0 + r) * NH + h];
        if (actv[r] != 0.f) ridx[nact++] = r;
    }
#pragma unroll
    for (int r = 0; r < QB; r++)
        if (actv[r] == 0.f) {
            size_t idx = (size_t)(t0 + r) * HH + h * HD + tid;
            oh[idx] = __float2bfloat16(0.f);
            ol[idx] = __float2bfloat16(0.f);
        }
    if (nact == 0) return;

    if (nact <= 2)
        attn_body<2>(q, k, v, amask, oh, ol, qs, P, red, t0, h, tid, nact, ridx);
    else if (nact <= 4)
        attn_body<4>(q, k, v, amask, oh, ol, qs, P, red, t0, h, tid, nact, ridx);
    else
        attn_body<8>(q, k, v, amask, oh, ol, qs, P, red, t0, h, tid, nact, ridx);
}

// ---------------- top-k radix select machinery ----------------
__device__ __forceinline__ unsigned fkey(float x) {
    unsigned b = __float_as_uint(x);
    return (b & 0x80000000u) ? ~b : (b | 0x80000000u);
}
__device__ __forceinline__ float unfkey(unsigned k) {
    unsigned b = (k & 0x80000000u) ? (k & 0x7fffffffu) : ~k;
    return __uint_as_float(b);
}

__global__ void mlp_thresh_kernel(const float* __restrict__ logits,
                                  float* __restrict__ thr) {
    int row = blockIdx.x;
    const float* lr = logits + (size_t)row * II;
    __shared__ unsigned hist[256];
    __shared__ unsigned sh_sel, sh_kk;
    int tid = threadIdx.x;
    unsigned prefix = 0;
    unsigned kk = MLP_TOPK;
    for (int shift = 24; shift >= 0; shift -= 8) {
        hist[tid] = 0;
        __syncthreads();
        for (int i = tid; i < II; i += 256) {
            unsigned u = fkey(lr[i]);
            bool ok = (shift == 24) || ((u >> (shift + 8)) == prefix);
            if (ok) atomicAdd(&hist[(u >> shift) & 255u], 1u);
        }
        __syncthreads();
        if (tid == 0) {
            unsigned c = 0;
            int sel = 0;
            for (int b = 255; b >= 0; b--) {
                c += hist[b];
                if (c >= kk) { sel = b; break; }
            }
            sh_sel = (unsigned)sel;
            sh_kk = kk - (c - hist[sel]);
        }
        __syncthreads();
        prefix = (prefix << 8) | sh_sel;
        kk = sh_kk;
        __syncthreads();
    }
    if (tid == 0) thr[row] = unfkey(prefix);
}

#define BAND 4e-3f
__global__ void mlp_correct_kernel(float* __restrict__ mlog,
                                   const float* __restrict__ hs,
                                   const float* __restrict__ w,
                                   const float* __restrict__ b,
                                   const float* __restrict__ thr) {
    int row = blockIdx.x;
    int tid = threadIdx.x;
    __shared__ int cnt;
    __shared__ int idxs[1024];
    if (tid == 0) cnt = 0;
    __syncthreads();
    float th = thr[row];
    float* lr = mlog + (size_t)row * II;
    for (int i = tid; i < II; i += 256) {
        if (fabsf(lr[i] - th) <= BAND) {
            int p = atomicAdd(&cnt, 1);
            if (p < 1024) idxs[p] = i;
        }
    }
    __syncthreads();
    int n = cnt < 1024 ? cnt : 1024;
    int warp = tid >> 5, lane = tid & 31;
    const float* hsr = hs + (size_t)row * HH;
    for (int c = warp; c < n; c += 8) {
        int i = idxs[c];
        const float* wr = w + (size_t)i * HH;
        float s = 0.f;
        for (int kk = lane; kk < HH; kk += 32) s += hsr[kk] * wr[kk];
        for (int o = 16; o > 0; o >>= 1) s += __shfl_xor_sync(0xffffffffu, s, o);
        if (lane == 0) lr[i] = s + b[i];
    }
}

__global__ void mlp_topk_kernel(const float* __restrict__ logits,
                                float* __restrict__ mask) {
    int row = blockIdx.x;
    const float* lr = logits + (size_t)row * II;
    __shared__ unsigned hist[256];
    __shared__ unsigned sh_sel, sh_kk;
    __shared__ unsigned sh_cnt[2];
    int tid = threadIdx.x;
    unsigned prefix = 0;
    unsigned kk = MLP_TOPK;
    for (int shift = 24; shift >= 0; shift -= 8) {
        hist[tid] = 0;
        __syncthreads();
        for (int i = tid; i < II; i += 256) {
            unsigned u = fkey(lr[i]);
            bool ok = (shift == 24) || ((u >> (shift + 8)) == prefix);
            if (ok) atomicAdd(&hist[(u >> shift) & 255u], 1u);
        }
        __syncthreads();
        if (tid == 0) {
            unsigned c = 0;
            int sel = 0;
            for (int b = 255; b >= 0; b--) {
                c += hist[b];
                if (c >= kk) { sel = b; break; }
            }
            sh_sel = (unsigned)sel;
            sh_kk = kk - (c - hist[sel]);
        }
        __syncthreads();
        prefix = (prefix << 8) | sh_sel;
        kk = sh_kk;
        __syncthreads();
    }
    unsigned thresh = prefix;
    if (tid < 2) sh_cnt[tid] = 0;
    __syncthreads();
    unsigned lg = 0, le = 0;
    for (int i = tid; i < II; i += 256) {
        unsigned u = fkey(lr[i]);
        if (u > thresh) lg++;
        else if (u == thresh) le++;
    }
    atomicAdd(&sh_cnt[0], lg);
    atomicAdd(&sh_cnt[1], le);
    __syncthreads();
    unsigned g = sh_cnt[0], e = sh_cnt[1];
    float* mr = mask + (size_t)row * II;
    if (g + e == MLP_TOPK) {
        for (int i = tid; i < II; i += 256)
            mr[i] = (fkey(lr[i]) >= thresh) ? 1.f : 0.f;
    } else {
        for (int i = tid; i < II; i += 256)
            mr[i] = (fkey(lr[i]) > thresh) ? 1.f : 0.f;
        __syncthreads();
        if (tid == 0) {
            unsigned quota = MLP_TOPK - g;
            for (int i = 0; i < II && quota > 0; i++) {
                if (fkey(lr[i]) == thresh) { mr[i] = 1.f; quota--; }
            }
        }
    }
}

// ---------------- silu * up * mask -> inter bf16 hi/lo ----------------
__global__ void silu_mul_mask_kernel(const float* __restrict__ gate,
                                     const float* __restrict__ up,
                                     const float* __restrict__ mask,
                                     __nv_bfloat16* __restrict__ ih,
                                     __nv_bfloat16* __restrict__ il, int n4) {
    int i = blockIdx.x * 256 + threadIdx.x;
    if (i < n4) {
        float4 x = ((const float4*)gate)[i];
        float4 u = ((const float4*)up)[i];
        float4 m = ((const float4*)mask)[i];
        float4 r;
        r.x = x.x / (1.f + __expf(-x.x)) * u.x * m.x;
        r.y = x.y / (1.f + __expf(-x.y)) * u.y * m.y;
        r.z = x.z / (1.f + __expf(-x.z)) * u.z * m.z;
        r.w = x.w / (1.f + __expf(-x.w)) * u.w * m.w;
        uint2 h, l;
        split4(r, h, l);
        ((uint2*)ih)[i] = h;
        ((uint2*)il)[i] = l;
    }
}

// ---------------- launch ----------------
extern "C" void kernel_launch(void* const* d_in, const int* in_sizes, int n_in,
                              void* d_out, int out_size) {
    const float* hidden = (const float*)d_in[0];
    const int* amask = (const int*)d_in[1];
    const int* pos = (const int*)d_in[2];
    const float* wq = (const float*)d_in[3];
    const float* wk = (const float*)d_in[4];
    const float* wv = (const float*)d_in[5];
    const float* wo = (const float*)d_in[6];
    const float* w_gate = (const float*)d_in[7];
    const float* w_up = (const float*)d_in[8];
    const float* w_down = (const float*)d_in[9];
    const float* ln1 = (const float*)d_in[10];
    const float* ln2 = (const float*)d_in[11];
    const float* apw = (const float*)d_in[12];
    const float* apb = (const float*)d_in[13];
    const float* mpw = (const float*)d_in[14];
    const float* mpb = (const float*)d_in[15];
    float* out = (float*)d_out;

    float *hs, *q, *k, *v, *res2, *hlog, *hmask, *mlog, *fcm, *gate, *up, *thr;
    cudaGetSymbolAddress((void**)&hs, g_hs);
    cudaGetSymbolAddress((void**)&q, g_q);
    cudaGetSymbolAddress((void**)&k, g_k);
    cudaGetSymbolAddress((void**)&v, g_v);
    cudaGetSymbolAddress((void**)&res2, g_res2);
    cudaGetSymbolAddress((void**)&hlog, g_hlogit);
    cudaGetSymbolAddress((void**)&hmask, g_headmask);
    cudaGetSymbolAddress((void**)&mlog, g_mlogit);
    cudaGetSymbolAddress((void**)&fcm, g_fcmask);
    cudaGetSymbolAddress((void**)&gate, g_gate);
    cudaGetSymbolAddress((void**)&up, g_up);
    cudaGetSymbolAddress((void**)&thr, g_thr);

    __nv_bfloat16 *hs_h, *hs_l, *at_h, *at_l, *in_h, *in_l;
    __nv_bfloat16 *wq_h, *wq_l, *wk_h, *wk_l, *wv_h, *wv_l, *wo_h, *wo_l;
    __nv_bfloat16 *mpw_h, *mpw_l, *wg_h, *wg_l, *wu_h, *wu_l, *wd_h, *wd_l;
    cudaGetSymbolAddress((void**)&hs_h, g_hs_h);
    cudaGetSymbolAddress((void**)&hs_l, g_hs_l);
    cudaGetSymbolAddress((void**)&at_h, g_attn_h);
    cudaGetSymbolAddress((void**)&at_l, g_attn_l);
    cudaGetSymbolAddress((void**)&in_h, g_int_h);
    cudaGetSymbolAddress((void**)&in_l, g_int_l);
    cudaGetSymbolAddress((void**)&wq_h, g_wq_h);
    cudaGetSymbolAddress((void**)&wq_l, g_wq_l);
    cudaGetSymbolAddress((void**)&wk_h, g_wk_h);
    cudaGetSymbolAddress((void**)&wk_l, g_wk_l);
    cudaGetSymbolAddress((void**)&wv_h, g_wv_h);
    cudaGetSymbolAddress((void**)&wv_l, g_wv_l);
    cudaGetSymbolAddress((void**)&wo_h, g_wo_h);
    cudaGetSymbolAddress((void**)&wo_l, g_wo_l);
    cudaGetSymbolAddress((void**)&mpw_h, g_mpw_h);
    cudaGetSymbolAddress((void**)&mpw_l, g_mpw_l);
    cudaGetSymbolAddress((void**)&wg_h, g_wg_h);
    cudaGetSymbolAddress((void**)&wg_l, g_wg_l);
    cudaGetSymbolAddress((void**)&wu_h, g_wu_h);
    cudaGetSymbolAddress((void**)&wu_l, g_wu_l);
    cudaGetSymbolAddress((void**)&wd_h, g_wd_h);
    cudaGetSymbolAddress((void**)&wd_l, g_wd_l);

    const int SMEM_B = 8 * HBUF * (int)sizeof(__nv_bfloat16);   // 81920 B
    cudaFuncSetAttribute(bf16gemm_nt,
                         cudaFuncAttributeMaxDynamicSharedMemorySize, SMEM_B);
    cudaFuncSetAttribute(qkv_gemm,
                         cudaFuncAttributeMaxDynamicSharedMemorySize, SMEM_B);
    cudaFuncSetAttribute(mlp3_gemm,
                         cudaFuncAttributeMaxDynamicSharedMemorySize, SMEM_B);
    const int SMEM_A = (QB * HD + TT * QB) * (int)sizeof(float);  // 69632 B
    cudaFuncSetAttribute(attention8_kernel,
                         cudaFuncAttributeMaxDynamicSharedMemorySize, SMEM_A);

    // --- split all weights (const per launch, recomputed for determinism) ---
    const int NHH4 = HH * HH / 4;
    const int NIH4 = II * HH / 4;
    split_kernel<<<(NHH4 + 255) / 256, 256>>>(wq, wq_h, wq_l, NHH4);
    split_kernel<<<(NHH4 + 255) / 256, 256>>>(wk, wk_h, wk_l, NHH4);
    split_kernel<<<(NHH4 + 255) / 256, 256>>>(wv, wv_h, wv_l, NHH4);
    split_kernel<<<(NHH4 + 255) / 256, 256>>>(wo, wo_h, wo_l, NHH4);
    split_kernel<<<(NIH4 + 255) / 256, 256>>>(mpw, mpw_h, mpw_l, NIH4);
    split_kernel<<<(NIH4 + 255) / 256, 256>>>(w_gate, wg_h, wg_l, NIH4);
    split_kernel<<<(NIH4 + 255) / 256, 256>>>(w_up, wu_h, wu_l, NIH4);
    split_kernel<<<(NIH4 + 255) / 256, 256>>>(w_down, wd_h, wd_l, NIH4);

    rmsnorm_kernel<<<TT, 256>>>(hidden, ln1, hs, hs_h, hs_l);
    qkv_gemm<<<dim3(HH / 128, TT / 128, 3), 512, SMEM_B>>>(hs_h, hs_l, q, k, v);
    rope_kernel<<<(TT * NH * 64 + 255) / 256, 256>>>(q, k, pos);
    attn_pred_kernel<<<TT, 256>>>(hs, apw, apb, hlog);
    head_mask_kernel<<<TT, 32>>>(hlog, hmask);
    attention8_kernel<<<dim3(TT / QB, NH), 128, SMEM_A>>>(q, k, v, hmask, amask,
                                                          at_h, at_l);
    bf16gemm_nt<<<dim3(HH / 128, TT / 128), 512, SMEM_B>>>(
        at_h, at_l, wo_h, wo_l, nullptr, hidden, res2, HH, HH);
    rmsnorm_kernel<<<TT, 256>>>(res2, ln2, hs, hs_h, hs_l);
    mlp3_gemm<<<dim3(II / 128, TT / 128, 3), 512, SMEM_B>>>(hs_h, hs_l, mpb,
                                                            mlog, gate, up);
    mlp_thresh_kernel<<<TT, 256>>>(mlog, thr);
    mlp_correct_kernel<<<TT, 256>>>(mlog, hs, mpw, mpb, thr);
    mlp_topk_kernel<<<TT, 256>>>(mlog, fcm);
    silu_mul_mask_kernel<<<(TT * II / 4 + 255) / 256, 256>>>(
        gate, up, fcm, in_h, in_l, TT * II / 4);
    bf16gemm_nt<<<dim3(HH / 128, TT / 128), 512, SMEM_B>>>(
        in_h, in_l, wd_h, wd_l, nullptr, res2, out, HH, II);
}